// round 4
// baseline (speedup 1.0000x reference)
#include <cuda_runtime.h>
#include <cstdint>

// B=64, T=4096, D=64, token tile 64 (+2 halo), M padded to 80 for m16 tiles.
// Layout permutations (within-group, preserve group base):
//   P(k): 8-groups,  pos = 2*(k&3) + ((k>>2)&1)  -> A frags load as float2
//   Q(n): 32-groups, pos = 4*(n&7) + ((n>>3)&3)  -> B frags load as float4
#define AST 72            // activation row stride (A-frag float2 conflict-free)
#define PST 68            // PRE row stride (natural layout)
#define WST 68            // weight row stride (B-frag float4 conflict-free, 16B mult)
#define WSLOT (64 * WST)
#define PSLOT (66 * PST)

// shared memory layout (floats)
#define OFF_XS   0                 // [80][72] (k-permuted cols)
#define OFF_HS   5760              // [80][72] (k-permuted cols)
#define OFF_WT   11520             // 5 x [64][68] (P rows, Q cols, tf32)
#define OFF_PRE  33280             // 5 x [66][68] (natural)
#define OFF_BIAS 55720             // qb,kb,vb,ab,bb,pb : 6 x 64 (natural)
#define OFF_CW   56104             // qcw,kcw,vcw : 3 x 192
#define OFF_CB   56680             // qcb,kcb,vcb : 3 x 64
#define OFF_NG   56872             // norm_g, P-permuted
#define OFF_PNG  56936             // post_norm_g, natural
#define SMEM_FLOATS 57000          // 228,000 bytes

__device__ __forceinline__ int permP(int k) { return (k & ~7) | (((k & 3) << 1) | ((k >> 2) & 1)); }
__device__ __forceinline__ int permQ(int n) { return (n & ~31) | (((n & 7) << 2) | ((n >> 3) & 3)); }

__device__ __forceinline__ float sigm(float z) { return 1.0f / (1.0f + expf(-z)); }

__device__ __forceinline__ float wredsum(float v) {
#pragma unroll
    for (int o = 16; o; o >>= 1) v += __shfl_xor_sync(0xffffffffu, v, o);
    return v;
}

__device__ __forceinline__ unsigned f2tf(float f) {
    unsigned u;
    asm("cvt.rna.tf32.f32 %0, %1;" : "=r"(u) : "f"(f));
    return u;
}

__device__ __forceinline__ void mma8(float* d, unsigned a0, unsigned a1, unsigned a2, unsigned a3,
                                     unsigned b0, unsigned b1) {
    asm("mma.sync.aligned.m16n8k8.row.col.f32.tf32.tf32.f32 "
        "{%0,%1,%2,%3}, {%4,%5,%6,%7}, {%8,%9}, {%0,%1,%2,%3};"
        : "+f"(d[0]), "+f"(d[1]), "+f"(d[2]), "+f"(d[3])
        : "r"(a0), "r"(a1), "r"(a2), "r"(a3), "r"(b0), "r"(b1));
}

__global__ void __launch_bounds__(512, 1) gdn_kernel(
    const float* __restrict__ x,   const float* __restrict__ norm_g,
    const float* __restrict__ qw,  const float* __restrict__ qb,
    const float* __restrict__ kw,  const float* __restrict__ kb,
    const float* __restrict__ vw,  const float* __restrict__ vb,
    const float* __restrict__ qcw, const float* __restrict__ qcb,
    const float* __restrict__ kcw, const float* __restrict__ kcb,
    const float* __restrict__ vcw, const float* __restrict__ vcb,
    const float* __restrict__ aw,  const float* __restrict__ ab,
    const float* __restrict__ bw,  const float* __restrict__ bb,
    const float* __restrict__ png, const float* __restrict__ pw,
    const float* __restrict__ pb,  float* __restrict__ out)
{
    extern __shared__ float sm[];
    float* XS   = sm + OFF_XS;
    float* HS   = sm + OFF_HS;
    float* WT   = sm + OFF_WT;
    float* PRE  = sm + OFF_PRE;
    float* BIAS = sm + OFF_BIAS;
    float* CW   = sm + OFF_CW;
    float* CB   = sm + OFF_CB;
    float* NG   = sm + OFF_NG;   // P-permuted
    float* PNG  = sm + OFF_PNG;  // natural

    const int tid  = threadIdx.x;
    const int warp = tid >> 5;
    const int lane = tid & 31;
    const int g    = lane >> 2;
    const int tg   = lane & 3;
    const int b    = blockIdx.x >> 6;
    const int t0   = (blockIdx.x & 63) << 6;
    const long xbase = ((long)b * 4096 + t0) * 64;
    const bool zlo = (t0 == 0), zhi = (t0 + 64 == 4096);

    // ---- load x tile (k-permuted scatter), rows 0..65; rows 66..79 zero ----
    for (int idx = tid; idx < 80 * 16; idx += 512) {
        const int r = idx >> 4, c4 = idx & 15;
        const int gt = t0 - 1 + r;
        float4 v = make_float4(0.f, 0.f, 0.f, 0.f);
        if (r < 66 && gt >= 0 && gt < 4096)
            v = *(const float4*)(x + ((long)b * 4096 + gt) * 64 + c4 * 4);
        float* row = XS + r * AST;
        row[permP(c4 * 4 + 0)] = v.x;
        row[permP(c4 * 4 + 1)] = v.y;
        row[permP(c4 * 4 + 2)] = v.z;
        row[permP(c4 * 4 + 3)] = v.w;
    }

    // ---- transpose 5 weight matrices into WT (tf32, P rows, Q cols) ----
    {
        const float* wsrc[5] = { qw, kw, vw, aw, bw };
        for (int idx = tid; idx < 5 * 1024; idx += 512) {
            const int m  = idx >> 10;
            const int rm = idx & 1023;
            const int c  = rm & 63;           // output channel (n)
            const int k4 = rm >> 6;           // 0..15
            const float4 w4 = *(const float4*)(wsrc[m] + c * 64 + k4 * 4);
            float* dst = WT + m * WSLOT + permQ(c);
            dst[permP(4 * k4 + 0) * WST] = __uint_as_float(f2tf(w4.x));
            dst[permP(4 * k4 + 1) * WST] = __uint_as_float(f2tf(w4.y));
            dst[permP(4 * k4 + 2) * WST] = __uint_as_float(f2tf(w4.z));
            dst[permP(4 * k4 + 3) * WST] = __uint_as_float(f2tf(w4.w));
        }
    }
    if (tid < 64) {
        BIAS[tid]       = qb[tid];  BIAS[64 + tid]  = kb[tid];  BIAS[128 + tid] = vb[tid];
        BIAS[192 + tid] = ab[tid];  BIAS[256 + tid] = bb[tid];  BIAS[320 + tid] = pb[tid];
        CB[tid] = qcb[tid];  CB[64 + tid] = kcb[tid];  CB[128 + tid] = vcb[tid];
        NG[permP(tid)] = norm_g[tid];  PNG[tid] = png[tid];
    }
    if (tid >= 64 && tid < 256) {
        const int i = tid - 64;
        CW[i] = qcw[i]; CW[192 + i] = kcw[i]; CW[384 + i] = vcw[i];
    }
    __syncthreads();

    // ---- zc_rmsnorm(x) -> HS (permutation-invariant reductions; NG permuted) ----
    for (int r = warp; r < 80; r += 16) {
        const float a  = XS[r * AST + lane];
        const float bv = XS[r * AST + lane + 32];
        const float mean = wredsum(a + bv) * (1.0f / 64.0f);
        const float a0 = a - mean, b0 = bv - mean;
        const float ms = wredsum(a0 * a0 + b0 * b0) * (1.0f / 64.0f);
        const float inv = rsqrtf(ms + 1e-8f);
        HS[r * AST + lane]      = a0 * inv * NG[lane];
        HS[r * AST + lane + 32] = b0 * inv * NG[lane + 32];
    }
    __syncthreads();

    // ---- phase-1: 25 warp-tiles m16 x n64 x k64 ----
    for (int tt = warp; tt < 25; tt += 16) {
        const int mat = tt / 5, mt = tt % 5;
        const float* A  = (mat < 3) ? HS : XS;
        const float* Ab = A + mt * 16 * AST;
        const float* Wb = WT + mat * WSLOT;

        float acc[8][4];
#pragma unroll
        for (int i = 0; i < 8; ++i)
#pragma unroll
            for (int j = 0; j < 4; ++j) acc[i][j] = 0.f;

#pragma unroll
        for (int kk = 0; kk < 64; kk += 8) {
            // A frags: float2 = (k=kk+tg, k=kk+tg+4) thanks to P layout
            const float2 aLo = *(const float2*)(Ab + g * AST + kk + 2 * tg);
            const float2 aHi = *(const float2*)(Ab + (g + 8) * AST + kk + 2 * tg);
            const unsigned a0 = f2tf(aLo.x), a2 = f2tf(aLo.y);
            const unsigned a1 = f2tf(aHi.x), a3 = f2tf(aHi.y);
            // B frags: per 32-col group, float4 covers 4 n-chunks (Q layout);
            // P layout puts k=kk+tg at row kk+2tg and k=kk+tg+4 at row kk+2tg+1.
            const float* r0p = Wb + (kk + 2 * tg) * WST + g * 4;
            const float* r1p = r0p + WST;
#pragma unroll
            for (int G = 0; G < 2; ++G) {
                const float4 b0v = *(const float4*)(r0p + G * 32);
                const float4 b1v = *(const float4*)(r1p + G * 32);
                mma8(acc[G * 4 + 0], a0, a1, a2, a3, __float_as_uint(b0v.x), __float_as_uint(b1v.x));
                mma8(acc[G * 4 + 1], a0, a1, a2, a3, __float_as_uint(b0v.y), __float_as_uint(b1v.y));
                mma8(acc[G * 4 + 2], a0, a1, a2, a3, __float_as_uint(b0v.z), __float_as_uint(b1v.z));
                mma8(acc[G * 4 + 3], a0, a1, a2, a3, __float_as_uint(b0v.w), __float_as_uint(b1v.w));
            }
        }
        // epilogue -> PRE[mat] (natural layout), conv-edge rows zeroed for q/k/v
        float* O = PRE + mat * PSLOT;
        const float* bias = BIAS + mat * 64;
        const bool qkv = (mat < 3);
        const int rA = mt * 16 + g, rB = rA + 8;
#pragma unroll
        for (int nt = 0; nt < 8; ++nt) {
            const int c0 = nt * 8 + 2 * tg;
            const float b0v = bias[c0], b1v = bias[c0 + 1];
            if (rA < 66) {
                float2 v = make_float2(acc[nt][0] + b0v, acc[nt][1] + b1v);
                if (qkv && ((zlo && rA == 0) || (zhi && rA == 65))) v = make_float2(0.f, 0.f);
                *(float2*)(O + rA * PST + c0) = v;
            }
            if (rB < 66) {
                float2 v = make_float2(acc[nt][2] + b0v, acc[nt][3] + b1v);
                if (qkv && ((zlo && rB == 0) || (zhi && rB == 65))) v = make_float2(0.f, 0.f);
                *(float2*)(O + rB * PST + c0) = v;
            }
        }
    }
    __syncthreads();

    // ---- transpose pw into WT slot 0 (tf32, P rows, Q cols) ----
    for (int idx = tid; idx < 1024; idx += 512) {
        const int c = idx & 63, k4 = idx >> 6;
        const float4 w4 = *(const float4*)(pw + c * 64 + k4 * 4);
        float* dst = WT + permQ(c);
        dst[permP(4 * k4 + 0) * WST] = __uint_as_float(f2tf(w4.x));
        dst[permP(4 * k4 + 1) * WST] = __uint_as_float(f2tf(w4.y));
        dst[permP(4 * k4 + 2) * WST] = __uint_as_float(f2tf(w4.z));
        dst[permP(4 * k4 + 3) * WST] = __uint_as_float(f2tf(w4.w));
    }

    // ---- per-token stage -> HS (k-permuted writes) ----
    {
        const float* QP = PRE;
        const float* KP = PRE + PSLOT;
        const float* VP = PRE + 2 * PSLOT;
        const float* AP = PRE + 3 * PSLOT;
        const float* BP = PRE + 4 * PSLOT;
        const int pl0 = permP(lane), pl1 = permP(lane + 32);
        for (int jj = 1 + warp; jj < 65; jj += 16) {
            float qv[2], kv[2], vv[2];
#pragma unroll
            for (int h = 0; h < 2; ++h) {
                const int c = lane + 32 * h;
                const float qm = QP[(jj - 1) * PST + c], q0 = QP[jj * PST + c], qp = QP[(jj + 1) * PST + c];
                qv[h] = sigm(CW[c * 3 + 0] * qm + CW[c * 3 + 1] * q0 + CW[c * 3 + 2] * qp + CB[c]);
                const float km = KP[(jj - 1) * PST + c], k0 = KP[jj * PST + c], kp = KP[(jj + 1) * PST + c];
                kv[h] = sigm(CW[192 + c * 3 + 0] * km + CW[192 + c * 3 + 1] * k0 + CW[192 + c * 3 + 2] * kp + CB[64 + c]);
                const float vm = VP[(jj - 1) * PST + c], v0 = VP[jj * PST + c], vp = VP[(jj + 1) * PST + c];
                vv[h] = sigm(CW[384 + c * 3 + 0] * vm + CW[384 + c * 3 + 1] * v0 + CW[384 + c * 3 + 2] * vp + CB[128 + c]);
            }
            const float qi = rsqrtf(wredsum(qv[0] * qv[0] + qv[1] * qv[1]) + 1e-8f);
            const float ki = rsqrtf(wredsum(kv[0] * kv[0] + kv[1] * kv[1]) + 1e-8f);
            float d2[2];
#pragma unroll
            for (int h = 0; h < 2; ++h) {
                const int c = lane + 32 * h;
                const float delta = (qv[h] * qi) * ((kv[h] * ki) * vv[h]);
                d2[h] = tanhf(AP[jj * PST + c]) * delta + BP[jj * PST + c];
            }
            const float mean = wredsum(d2[0] + d2[1]) * (1.0f / 64.0f);
            const float e0 = d2[0] - mean, e1 = d2[1] - mean;
            const float ms = wredsum(e0 * e0 + e1 * e1) * (1.0f / 64.0f);
            const float inv = rsqrtf(ms + 1e-8f);
            HS[(jj - 1) * AST + pl0] = e0 * inv * PNG[lane];
            HS[(jj - 1) * AST + pl1] = e1 * inv * PNG[lane + 32];
        }
    }
    __syncthreads();

    // ---- final GEMM: 16 warp-tiles m16 x n16 x k64 + fused gating epilogue ----
    {
        const int mt   = warp >> 2;      // token rows mt*16..+15
        const int nt16 = warp & 3;       // n16 chunk
        const int Gf   = nt16 >> 1;      // 32-col group
        const int ps   = nt16 & 1;       // pair-select within group
        const float* Ab = HS + mt * 16 * AST;
        const float* Wb = WT;

        float acc[2][4];
#pragma unroll
        for (int i = 0; i < 2; ++i)
#pragma unroll
            for (int j = 0; j < 4; ++j) acc[i][j] = 0.f;

#pragma unroll
        for (int kk = 0; kk < 64; kk += 8) {
            const float2 aLo = *(const float2*)(Ab + g * AST + kk + 2 * tg);
            const float2 aHi = *(const float2*)(Ab + (g + 8) * AST + kk + 2 * tg);
            const unsigned a0 = f2tf(aLo.x), a2 = f2tf(aLo.y);
            const unsigned a1 = f2tf(aHi.x), a3 = f2tf(aHi.y);
            const float* r0p = Wb + (kk + 2 * tg) * WST + Gf * 32 + g * 4;
            const float4 b0v = *(const float4*)(r0p);
            const float4 b1v = *(const float4*)(r0p + WST);
            const float b0s[4] = { b0v.x, b0v.y, b0v.z, b0v.w };
            const float b1s[4] = { b1v.x, b1v.y, b1v.z, b1v.w };
            mma8(acc[0], a0, a1, a2, a3, __float_as_uint(b0s[2 * ps + 0]), __float_as_uint(b1s[2 * ps + 0]));
            mma8(acc[1], a0, a1, a2, a3, __float_as_uint(b0s[2 * ps + 1]), __float_as_uint(b1s[2 * ps + 1]));
        }
#pragma unroll
        for (int nn = 0; nn < 2; ++nn) {
            const int col = nt16 * 16 + nn * 8 + 2 * tg;
            const float pb0 = BIAS[320 + col], pb1 = BIAS[320 + col + 1];
            const int pc0 = permP(col), pc1 = permP(col + 1);
#pragma unroll
            for (int h = 0; h < 2; ++h) {
                const int row = mt * 16 + g + 8 * h;     // token t0 + row
                const float d0 = acc[nn][2 * h + 0] + pb0;
                const float d1 = acc[nn][2 * h + 1] + pb1;
                const float g0 = sigm(d0 * sigm(d0));
                const float g1 = sigm(d1 * sigm(d1));
                const float xv0 = XS[(row + 1) * AST + pc0];
                const float xv1 = XS[(row + 1) * AST + pc1];
                float2 o = make_float2(xv0 + g0 * d0, xv1 + g1 * d1);
                *(float2*)(out + xbase + (long)row * 64 + col) = o;
            }
        }
    }
}

extern "C" void kernel_launch(void* const* d_in, const int* in_sizes, int n_in,
                              void* d_out, int out_size)
{
    const float* x      = (const float*)d_in[0];
    const float* norm_g = (const float*)d_in[1];
    const float* qw  = (const float*)d_in[2];
    const float* qb  = (const float*)d_in[3];
    const float* kw  = (const float*)d_in[4];
    const float* kb  = (const float*)d_in[5];
    const float* vw  = (const float*)d_in[6];
    const float* vb  = (const float*)d_in[7];
    const float* qcw = (const float*)d_in[8];
    const float* qcb = (const float*)d_in[9];
    const float* kcw = (const float*)d_in[10];
    const float* kcb = (const float*)d_in[11];
    const float* vcw = (const float*)d_in[12];
    const float* vcb = (const float*)d_in[13];
    const float* aw  = (const float*)d_in[14];
    const float* ab  = (const float*)d_in[15];
    const float* bw  = (const float*)d_in[16];
    const float* bb  = (const float*)d_in[17];
    const float* png = (const float*)d_in[18];
    const float* pw  = (const float*)d_in[19];
    const float* pb  = (const float*)d_in[20];
    float* out = (float*)d_out;

    const int smem_bytes = SMEM_FLOATS * (int)sizeof(float);
    cudaFuncSetAttribute(gdn_kernel, cudaFuncAttributeMaxDynamicSharedMemorySize, smem_bytes);
    gdn_kernel<<<4096, 512, smem_bytes>>>(
        x, norm_g, qw, qb, kw, kb, vw, vb, qcw, qcb, kcw, kcb, vcw, vcb,
        aw, ab, bw, bb, png, pw, pb, out);
}

// round 5
// speedup vs baseline: 1.1251x; 1.1251x over previous
#include <cuda_runtime.h>
#include <cstdint>

// B=64, T=4096, D=64. Token tile 64 (+2 halo rows), M padded to 80 (5 m16-tiles).
// 640 threads = 20 warps. Phase-1: 20 jobs = 5 matrices x 4 n16-chunks, B in regs.
#define AST 68            // activation row stride: banks (4g+tg)%32 unique for A frags
#define PST 68            // preactivation row stride
#define WST 68            // transposed-weight row stride
#define WSLOT (64 * WST)
#define PSLOT (66 * PST)

// shared memory layout (floats)
#define OFF_XS   0                 // [80][68] fp32
#define OFF_HS   5440              // [80][68] tf32 bits
#define OFF_WT   10880             // 5 x [64][68] tf32 (transposed)
#define OFF_PRE  32640             // 5 x [66][68] fp32
#define OFF_BIAS 55080             // qb,kb,vb,ab,bb,pb : 6 x 64
#define OFF_CW   55464             // qcw,kcw,vcw : 3 x 192
#define OFF_CB   56040             // qcb,kcb,vcb : 3 x 64
#define OFF_NG   56232
#define OFF_PNG  56296
#define SMEM_FLOATS 56360          // 225,440 bytes

__device__ __forceinline__ float sigm(float z) { return 1.0f / (1.0f + expf(-z)); }

__device__ __forceinline__ float wredsum(float v) {
#pragma unroll
    for (int o = 16; o; o >>= 1) v += __shfl_xor_sync(0xffffffffu, v, o);
    return v;
}

__device__ __forceinline__ unsigned f2tf(float f) {
    unsigned u;
    asm("cvt.rna.tf32.f32 %0, %1;" : "=r"(u) : "f"(f));
    return u;
}

__device__ __forceinline__ void mma8(float* d, unsigned a0, unsigned a1, unsigned a2, unsigned a3,
                                     unsigned b0, unsigned b1) {
    asm("mma.sync.aligned.m16n8k8.row.col.f32.tf32.tf32.f32 "
        "{%0,%1,%2,%3}, {%4,%5,%6,%7}, {%8,%9}, {%0,%1,%2,%3};"
        : "+f"(d[0]), "+f"(d[1]), "+f"(d[2]), "+f"(d[3])
        : "r"(a0), "r"(a1), "r"(a2), "r"(a3), "r"(b0), "r"(b1));
}

__global__ void __launch_bounds__(640, 1) gdn_kernel(
    const float* __restrict__ x,   const float* __restrict__ norm_g,
    const float* __restrict__ qw,  const float* __restrict__ qb,
    const float* __restrict__ kw,  const float* __restrict__ kb,
    const float* __restrict__ vw,  const float* __restrict__ vb,
    const float* __restrict__ qcw, const float* __restrict__ qcb,
    const float* __restrict__ kcw, const float* __restrict__ kcb,
    const float* __restrict__ vcw, const float* __restrict__ vcb,
    const float* __restrict__ aw,  const float* __restrict__ ab,
    const float* __restrict__ bw,  const float* __restrict__ bb,
    const float* __restrict__ png, const float* __restrict__ pw,
    const float* __restrict__ pb,  float* __restrict__ out)
{
    extern __shared__ float sm[];
    float* XS   = sm + OFF_XS;
    float* HS   = sm + OFF_HS;     // holds tf32-bit floats
    float* WT   = sm + OFF_WT;
    float* PRE  = sm + OFF_PRE;
    float* BIAS = sm + OFF_BIAS;
    float* CW   = sm + OFF_CW;
    float* CB   = sm + OFF_CB;
    float* NG   = sm + OFF_NG;
    float* PNG  = sm + OFF_PNG;

    const int tid  = threadIdx.x;
    const int warp = tid >> 5;
    const int lane = tid & 31;
    const int g    = lane >> 2;
    const int tg   = lane & 3;
    const int b    = blockIdx.x >> 6;
    const int t0   = (blockIdx.x & 63) << 6;
    const long xbase = ((long)b * 4096 + t0) * 64;
    const bool zlo = (t0 == 0), zhi = (t0 + 64 == 4096);

    // ---- load x tile rows 0..65 <-> tokens t0-1..t0+64; rows 66..79 zero ----
    for (int idx = tid; idx < 80 * 16; idx += 640) {
        const int r = idx >> 4, c4 = idx & 15;
        const int gt = t0 - 1 + r;
        float4 v = make_float4(0.f, 0.f, 0.f, 0.f);
        if (r < 66 && gt >= 0 && gt < 4096)
            v = *(const float4*)(x + ((long)b * 4096 + gt) * 64 + c4 * 4);
        *(float4*)(XS + r * AST + c4 * 4) = v;
    }

    // ---- transpose 5 weight matrices into WT (tf32): Wt[k][c] = W[c][k] ----
    {
        const float* wsrc[5] = { qw, kw, vw, aw, bw };
        for (int idx = tid; idx < 5 * 1024; idx += 640) {
            const int m  = idx >> 10;
            const int rm = idx & 1023;
            const int c  = rm & 63;
            const int k4 = rm >> 6;
            const float4 w4 = *(const float4*)(wsrc[m] + c * 64 + k4 * 4);
            float* dst = WT + m * WSLOT + c;
            dst[(4 * k4 + 0) * WST] = __uint_as_float(f2tf(w4.x));
            dst[(4 * k4 + 1) * WST] = __uint_as_float(f2tf(w4.y));
            dst[(4 * k4 + 2) * WST] = __uint_as_float(f2tf(w4.z));
            dst[(4 * k4 + 3) * WST] = __uint_as_float(f2tf(w4.w));
        }
    }
    if (tid < 64) {
        BIAS[tid]       = qb[tid];  BIAS[64 + tid]  = kb[tid];  BIAS[128 + tid] = vb[tid];
        BIAS[192 + tid] = ab[tid];  BIAS[256 + tid] = bb[tid];  BIAS[320 + tid] = pb[tid];
        CB[tid] = qcb[tid];  CB[64 + tid] = kcb[tid];  CB[128 + tid] = vcb[tid];
        NG[tid] = norm_g[tid];  PNG[tid] = png[tid];
    }
    if (tid >= 64 && tid < 256) {
        const int i = tid - 64;
        CW[i] = qcw[i]; CW[192 + i] = kcw[i]; CW[384 + i] = vcw[i];
    }
    __syncthreads();

    // ---- zc_rmsnorm(x) -> HS as tf32 bits (rows 66..79 stay zero) ----
    for (int r = warp; r < 80; r += 20) {
        const float a  = XS[r * AST + lane];
        const float bv = XS[r * AST + lane + 32];
        const float mean = wredsum(a + bv) * (1.0f / 64.0f);
        const float a0 = a - mean, b0 = bv - mean;
        const float ms = wredsum(a0 * a0 + b0 * b0) * (1.0f / 64.0f);
        const float inv = rsqrtf(ms + 1e-8f);
        HS[r * AST + lane]      = __uint_as_float(f2tf(a0 * inv * NG[lane]));
        HS[r * AST + lane + 32] = __uint_as_float(f2tf(b0 * inv * NG[lane + 32]));
    }
    __syncthreads();

    // ---- phase-1: 20 jobs = (matrix 0..4) x (n16 chunk 0..3); B frags in regs ----
    {
        const int mat = warp / 4;            // 0..4 : q,k,v,a,b
        const int n0  = (warp & 3) * 16;
        const float* Wb = WT + mat * WSLOT;
        const bool fromX = (mat >= 3);
        const float* A  = fromX ? XS : HS;

        // hoist B fragments: 32 words (k64 x n16 per-thread share)
        unsigned Bf[8][2][2];
#pragma unroll
        for (int k8 = 0; k8 < 8; ++k8) {
            const float* r0 = Wb + (8 * k8 + tg) * WST + n0 + g;
            const float* r1 = Wb + (8 * k8 + tg + 4) * WST + n0 + g;
            Bf[k8][0][0] = __float_as_uint(r0[0]);
            Bf[k8][0][1] = __float_as_uint(r1[0]);
            Bf[k8][1][0] = __float_as_uint(r0[8]);
            Bf[k8][1][1] = __float_as_uint(r1[8]);
        }

        float* O = PRE + mat * PSLOT;
        const float* bias = BIAS + mat * 64;
        const bool qkv = (mat < 3);

#pragma unroll
        for (int mt = 0; mt < 5; ++mt) {
            const float* Ab = A + mt * 16 * AST;
            float acc[2][4];
#pragma unroll
            for (int i = 0; i < 2; ++i)
#pragma unroll
                for (int j = 0; j < 4; ++j) acc[i][j] = 0.f;

#pragma unroll
            for (int k8 = 0; k8 < 8; ++k8) {
                const int kk = 8 * k8;
                unsigned a0, a1, a2, a3;
                if (fromX) {
                    a0 = f2tf(Ab[g * AST + kk + tg]);
                    a1 = f2tf(Ab[(g + 8) * AST + kk + tg]);
                    a2 = f2tf(Ab[g * AST + kk + tg + 4]);
                    a3 = f2tf(Ab[(g + 8) * AST + kk + tg + 4]);
                } else {
                    a0 = __float_as_uint(Ab[g * AST + kk + tg]);
                    a1 = __float_as_uint(Ab[(g + 8) * AST + kk + tg]);
                    a2 = __float_as_uint(Ab[g * AST + kk + tg + 4]);
                    a3 = __float_as_uint(Ab[(g + 8) * AST + kk + tg + 4]);
                }
                mma8(acc[0], a0, a1, a2, a3, Bf[k8][0][0], Bf[k8][0][1]);
                mma8(acc[1], a0, a1, a2, a3, Bf[k8][1][0], Bf[k8][1][1]);
            }
            const int rA = mt * 16 + g, rB = rA + 8;
#pragma unroll
            for (int nn = 0; nn < 2; ++nn) {
                const int c0 = n0 + nn * 8 + 2 * tg;
                const float b0v = bias[c0], b1v = bias[c0 + 1];
                if (rA < 66) {
                    float2 v = make_float2(acc[nn][0] + b0v, acc[nn][1] + b1v);
                    if (qkv && ((zlo && rA == 0) || (zhi && rA == 65))) v = make_float2(0.f, 0.f);
                    *(float2*)(O + rA * PST + c0) = v;
                }
                if (rB < 66) {
                    float2 v = make_float2(acc[nn][2] + b0v, acc[nn][3] + b1v);
                    if (qkv && ((zlo && rB == 0) || (zhi && rB == 65))) v = make_float2(0.f, 0.f);
                    *(float2*)(O + rB * PST + c0) = v;
                }
            }
        }
    }
    __syncthreads();

    // ---- transpose pw into WT slot 0 (tf32) ----
    for (int idx = tid; idx < 1024; idx += 640) {
        const int c = idx & 63, k4 = idx >> 6;
        const float4 w4 = *(const float4*)(pw + c * 64 + k4 * 4);
        float* dst = WT + c;
        dst[(4 * k4 + 0) * WST] = __uint_as_float(f2tf(w4.x));
        dst[(4 * k4 + 1) * WST] = __uint_as_float(f2tf(w4.y));
        dst[(4 * k4 + 2) * WST] = __uint_as_float(f2tf(w4.z));
        dst[(4 * k4 + 3) * WST] = __uint_as_float(f2tf(w4.w));
    }

    // ---- per-token stage -> HS (tf32 bits) ----
    {
        const float* QP = PRE;
        const float* KP = PRE + PSLOT;
        const float* VP = PRE + 2 * PSLOT;
        const float* AP = PRE + 3 * PSLOT;
        const float* BP = PRE + 4 * PSLOT;
        for (int jj = 1 + warp; jj < 65; jj += 20) {
            float qv[2], kv[2], vv[2];
#pragma unroll
            for (int h = 0; h < 2; ++h) {
                const int c = lane + 32 * h;
                const float qm = QP[(jj - 1) * PST + c], q0 = QP[jj * PST + c], qp = QP[(jj + 1) * PST + c];
                qv[h] = sigm(CW[c * 3 + 0] * qm + CW[c * 3 + 1] * q0 + CW[c * 3 + 2] * qp + CB[c]);
                const float km = KP[(jj - 1) * PST + c], k0 = KP[jj * PST + c], kp = KP[(jj + 1) * PST + c];
                kv[h] = sigm(CW[192 + c * 3 + 0] * km + CW[192 + c * 3 + 1] * k0 + CW[192 + c * 3 + 2] * kp + CB[64 + c]);
                const float vm = VP[(jj - 1) * PST + c], v0 = VP[jj * PST + c], vp = VP[(jj + 1) * PST + c];
                vv[h] = sigm(CW[384 + c * 3 + 0] * vm + CW[384 + c * 3 + 1] * v0 + CW[384 + c * 3 + 2] * vp + CB[128 + c]);
            }
            const float qi = rsqrtf(wredsum(qv[0] * qv[0] + qv[1] * qv[1]) + 1e-8f);
            const float ki = rsqrtf(wredsum(kv[0] * kv[0] + kv[1] * kv[1]) + 1e-8f);
            float d2[2];
#pragma unroll
            for (int h = 0; h < 2; ++h) {
                const int c = lane + 32 * h;
                const float delta = (qv[h] * qi) * ((kv[h] * ki) * vv[h]);
                d2[h] = tanhf(AP[jj * PST + c]) * delta + BP[jj * PST + c];
            }
            const float mean = wredsum(d2[0] + d2[1]) * (1.0f / 64.0f);
            const float e0 = d2[0] - mean, e1 = d2[1] - mean;
            const float ms = wredsum(e0 * e0 + e1 * e1) * (1.0f / 64.0f);
            const float inv = rsqrtf(ms + 1e-8f);
            HS[(jj - 1) * AST + lane]      = __uint_as_float(f2tf(e0 * inv * PNG[lane]));
            HS[(jj - 1) * AST + lane + 32] = __uint_as_float(f2tf(e1 * inv * PNG[lane + 32]));
        }
    }
    __syncthreads();

    // ---- final GEMM: 16 jobs m16 x n16 x k64 over warps 0..15, B(pw) in regs ----
    if (warp < 16) {
        const int mt  = warp >> 2;
        const int n0  = (warp & 3) * 16;

        unsigned Bf[8][2][2];
#pragma unroll
        for (int k8 = 0; k8 < 8; ++k8) {
            const float* r0 = WT + (8 * k8 + tg) * WST + n0 + g;
            const float* r1 = WT + (8 * k8 + tg + 4) * WST + n0 + g;
            Bf[k8][0][0] = __float_as_uint(r0[0]);
            Bf[k8][0][1] = __float_as_uint(r1[0]);
            Bf[k8][1][0] = __float_as_uint(r0[8]);
            Bf[k8][1][1] = __float_as_uint(r1[8]);
        }

        const float* Ab = HS + mt * 16 * AST;
        float acc[2][4];
#pragma unroll
        for (int i = 0; i < 2; ++i)
#pragma unroll
            for (int j = 0; j < 4; ++j) acc[i][j] = 0.f;

#pragma unroll
        for (int k8 = 0; k8 < 8; ++k8) {
            const int kk = 8 * k8;
            const unsigned a0 = __float_as_uint(Ab[g * AST + kk + tg]);
            const unsigned a1 = __float_as_uint(Ab[(g + 8) * AST + kk + tg]);
            const unsigned a2 = __float_as_uint(Ab[g * AST + kk + tg + 4]);
            const unsigned a3 = __float_as_uint(Ab[(g + 8) * AST + kk + tg + 4]);
            mma8(acc[0], a0, a1, a2, a3, Bf[k8][0][0], Bf[k8][0][1]);
            mma8(acc[1], a0, a1, a2, a3, Bf[k8][1][0], Bf[k8][1][1]);
        }
#pragma unroll
        for (int nn = 0; nn < 2; ++nn) {
            const int col = n0 + nn * 8 + 2 * tg;
            const float pb0 = BIAS[320 + col], pb1 = BIAS[320 + col + 1];
#pragma unroll
            for (int h = 0; h < 2; ++h) {
                const int row = mt * 16 + g + 8 * h;     // token t0 + row
                const float d0 = acc[nn][2 * h + 0] + pb0;
                const float d1 = acc[nn][2 * h + 1] + pb1;
                const float g0 = sigm(d0 * sigm(d0));
                const float g1 = sigm(d1 * sigm(d1));
                const float2 xv = *(const float2*)(XS + (row + 1) * AST + col);
                float2 o = make_float2(xv.x + g0 * d0, xv.y + g1 * d1);
                *(float2*)(out + xbase + (long)row * 64 + col) = o;
            }
        }
    }
}

extern "C" void kernel_launch(void* const* d_in, const int* in_sizes, int n_in,
                              void* d_out, int out_size)
{
    const float* x      = (const float*)d_in[0];
    const float* norm_g = (const float*)d_in[1];
    const float* qw  = (const float*)d_in[2];
    const float* qb  = (const float*)d_in[3];
    const float* kw  = (const float*)d_in[4];
    const float* kb  = (const float*)d_in[5];
    const float* vw  = (const float*)d_in[6];
    const float* vb  = (const float*)d_in[7];
    const float* qcw = (const float*)d_in[8];
    const float* qcb = (const float*)d_in[9];
    const float* kcw = (const float*)d_in[10];
    const float* kcb = (const float*)d_in[11];
    const float* vcw = (const float*)d_in[12];
    const float* vcb = (const float*)d_in[13];
    const float* aw  = (const float*)d_in[14];
    const float* ab  = (const float*)d_in[15];
    const float* bw  = (const float*)d_in[16];
    const float* bb  = (const float*)d_in[17];
    const float* png = (const float*)d_in[18];
    const float* pw  = (const float*)d_in[19];
    const float* pb  = (const float*)d_in[20];
    float* out = (float*)d_out;

    const int smem_bytes = SMEM_FLOATS * (int)sizeof(float);
    cudaFuncSetAttribute(gdn_kernel, cudaFuncAttributeMaxDynamicSharedMemorySize, smem_bytes);
    gdn_kernel<<<4096, 640, smem_bytes>>>(
        x, norm_g, qw, qb, kw, kb, vw, vb, qcw, qcb, kcw, kcb, vcw, vcb,
        aw, ab, bw, bb, png, pw, pb, out);
}

// round 6
// speedup vs baseline: 1.1596x; 1.0306x over previous
#include <cuda_runtime.h>
#include <cstdint>

// B=64, T=4096, D=64. Token tile 64 (+2 halo rows), M padded to 80 (5 m16-tiles).
// 640 threads = 20 warps.
// A operands live in mma-fragment layout: per m16-tile, per k8-step, 32 lanes x float4
// [a0,a1,a2,a3]; k8-stride 132 floats (33 float4) for bank spread on scatter-stores.
#define FRK 132
#define TSLOT (8 * FRK)    // 1056 floats per m16 tile
#define PST 68             // preactivation row stride
#define WST 72             // transposed-weight row stride: B-hoist banks 8*tg+g unique
#define WSLOT (64 * WST)
#define PSLOT (66 * PST)

// shared memory layout (floats)
#define OFF_XF   0                 // 5 x TSLOT (x raw, tf32 bits, fragment layout)
#define OFF_HF   5280              // 5 x TSLOT (h / delta-norm, tf32 bits, fragment)
#define OFF_WT   10560             // 5 x [64][72] tf32 (transposed)
#define OFF_PRE  33600             // 5 x [66][68] fp32
#define OFF_BIAS 56040             // qb,kb,vb,ab,bb,pb : 6 x 64
#define OFF_CW   56424             // qcw,kcw,vcw : 3 x 192
#define OFF_CB   57000             // qcb,kcb,vcb : 3 x 64
#define OFF_NG   57192
#define OFF_PNG  57256
#define SMEM_FLOATS 57320          // 229,280 bytes

__device__ __forceinline__ float sigm(float z) { return 1.0f / (1.0f + expf(-z)); }

__device__ __forceinline__ float wredsum(float v) {
#pragma unroll
    for (int o = 16; o; o >>= 1) v += __shfl_xor_sync(0xffffffffu, v, o);
    return v;
}

__device__ __forceinline__ unsigned f2tf(float f) {
    unsigned u;
    asm("cvt.rna.tf32.f32 %0, %1;" : "=r"(u) : "f"(f));
    return u;
}

// fragment scatter offset for value at (row-in-tile ri = r&15, col c)
__device__ __forceinline__ int frag_off(int gd, int hi, int c) {
    return (c >> 3) * FRK + (4 * gd + (c & 3)) * 4 + hi + 2 * ((c >> 2) & 1);
}

__device__ __forceinline__ void mma8(float* d, unsigned a0, unsigned a1, unsigned a2, unsigned a3,
                                     unsigned b0, unsigned b1) {
    asm("mma.sync.aligned.m16n8k8.row.col.f32.tf32.tf32.f32 "
        "{%0,%1,%2,%3}, {%4,%5,%6,%7}, {%8,%9}, {%0,%1,%2,%3};"
        : "+f"(d[0]), "+f"(d[1]), "+f"(d[2]), "+f"(d[3])
        : "r"(a0), "r"(a1), "r"(a2), "r"(a3), "r"(b0), "r"(b1));
}

__global__ void __launch_bounds__(640, 1) gdn_kernel(
    const float* __restrict__ x,   const float* __restrict__ norm_g,
    const float* __restrict__ qw,  const float* __restrict__ qb,
    const float* __restrict__ kw,  const float* __restrict__ kb,
    const float* __restrict__ vw,  const float* __restrict__ vb,
    const float* __restrict__ qcw, const float* __restrict__ qcb,
    const float* __restrict__ kcw, const float* __restrict__ kcb,
    const float* __restrict__ vcw, const float* __restrict__ vcb,
    const float* __restrict__ aw,  const float* __restrict__ ab,
    const float* __restrict__ bw,  const float* __restrict__ bb,
    const float* __restrict__ png, const float* __restrict__ pw,
    const float* __restrict__ pb,  float* __restrict__ out)
{
    extern __shared__ float sm[];
    float* XF   = sm + OFF_XF;
    float* HF   = sm + OFF_HF;
    float* WT   = sm + OFF_WT;
    float* PRE  = sm + OFF_PRE;
    float* BIAS = sm + OFF_BIAS;
    float* CW   = sm + OFF_CW;
    float* CB   = sm + OFF_CB;
    float* NG   = sm + OFF_NG;
    float* PNG  = sm + OFF_PNG;

    const int tid  = threadIdx.x;
    const int warp = tid >> 5;
    const int lane = tid & 31;
    const int g    = lane >> 2;
    const int tg   = lane & 3;
    const int b    = blockIdx.x >> 6;
    const int t0   = (blockIdx.x & 63) << 6;
    const long xbase = ((long)b * 4096 + t0) * 64;
    const bool zlo = (t0 == 0), zhi = (t0 + 64 == 4096);

    // ---- transpose 5 weight matrices into WT (tf32): Wt[k][c] = W[c][k] ----
    {
        const float* wsrc[5] = { qw, kw, vw, aw, bw };
        for (int idx = tid; idx < 5 * 1024; idx += 640) {
            const int m  = idx >> 10;
            const int rm = idx & 1023;
            const int c  = rm & 63;
            const int k4 = rm >> 6;
            const float4 w4 = *(const float4*)(wsrc[m] + c * 64 + k4 * 4);
            float* dst = WT + m * WSLOT + c;
            dst[(4 * k4 + 0) * WST] = __uint_as_float(f2tf(w4.x));
            dst[(4 * k4 + 1) * WST] = __uint_as_float(f2tf(w4.y));
            dst[(4 * k4 + 2) * WST] = __uint_as_float(f2tf(w4.z));
            dst[(4 * k4 + 3) * WST] = __uint_as_float(f2tf(w4.w));
        }
    }
    if (tid < 64) {
        BIAS[tid]       = qb[tid];  BIAS[64 + tid]  = kb[tid];  BIAS[128 + tid] = vb[tid];
        BIAS[192 + tid] = ab[tid];  BIAS[256 + tid] = bb[tid];  BIAS[320 + tid] = pb[tid];
        CB[tid] = qcb[tid];  CB[64 + tid] = kcb[tid];  CB[128 + tid] = vcb[tid];
        NG[tid] = norm_g[tid];  PNG[tid] = png[tid];
    }
    if (tid >= 64 && tid < 256) {
        const int i = tid - 64;
        CW[i] = qcw[i]; CW[192 + i] = kcw[i]; CW[384 + i] = vcw[i];
    }
    // NG needed before norm loop below -> sync now (also covers WT/PRE hazards later)
    __syncthreads();

    // ---- x load + zc_rmsnorm -> XF (raw x, tf32) and HF (h, tf32) fragments ----
    // halo row r <-> token t0-1+r; rows 66..79 zero pad.
    for (int r = warp; r < 80; r += 20) {
        const int gt = t0 - 1 + r;
        const bool valid = (r < 66) && (gt >= 0) && (gt < 4096);
        float a = 0.f, bv = 0.f;
        if (valid) {
            const float* xr = x + ((long)b * 4096 + gt) * 64;
            a  = xr[lane];
            bv = xr[lane + 32];
        }
        const int mt = r >> 4, gd = r & 7, hi = (r >> 3) & 1;
        const int o0 = frag_off(gd, hi, lane);
        const int o1 = frag_off(gd, hi, lane + 32);
        float* xf = XF + mt * TSLOT;
        float* hf = HF + mt * TSLOT;
        xf[o0] = __uint_as_float(f2tf(a));
        xf[o1] = __uint_as_float(f2tf(bv));
        const float mean = wredsum(a + bv) * (1.0f / 64.0f);
        const float am = a - mean, bm = bv - mean;
        const float ms = wredsum(am * am + bm * bm) * (1.0f / 64.0f);
        const float inv = rsqrtf(ms + 1e-8f);
        hf[o0] = __uint_as_float(f2tf(am * inv * NG[lane]));
        hf[o1] = __uint_as_float(f2tf(bm * inv * NG[lane + 32]));
    }
    __syncthreads();

    // ---- phase-1: 20 jobs = (matrix 0..4) x (n16 chunk 0..3) ----
    {
        const int mat = warp >> 2;           // 0..4
        const int n0  = (warp & 3) * 16;
        const float* Wb = WT + mat * WSLOT;
        const float* AF = (mat < 3) ? HF : XF;

        // B fragments hoisted: banks (8*tg+g) unique -> conflict-free
        unsigned Bf[8][2][2];
#pragma unroll
        for (int k8 = 0; k8 < 8; ++k8) {
            const float* r0 = Wb + (8 * k8 + tg) * WST + n0 + g;
            const float* r1 = r0 + 4 * WST;
            Bf[k8][0][0] = __float_as_uint(r0[0]);
            Bf[k8][0][1] = __float_as_uint(r1[0]);
            Bf[k8][1][0] = __float_as_uint(r0[8]);
            Bf[k8][1][1] = __float_as_uint(r1[8]);
        }

        float* O = PRE + mat * PSLOT;
        const float* bias = BIAS + mat * 64;
        const bool qkv = (mat < 3);

#pragma unroll
        for (int mt = 0; mt < 5; ++mt) {
            const float4* Afp = (const float4*)(AF + mt * TSLOT);
            float acc[2][4];
#pragma unroll
            for (int i = 0; i < 2; ++i)
#pragma unroll
                for (int j = 0; j < 4; ++j) acc[i][j] = 0.f;

#pragma unroll
            for (int k8 = 0; k8 < 8; ++k8) {
                const float4 av = Afp[k8 * 33 + lane];
                const unsigned a0 = __float_as_uint(av.x);
                const unsigned a1 = __float_as_uint(av.y);
                const unsigned a2 = __float_as_uint(av.z);
                const unsigned a3 = __float_as_uint(av.w);
                mma8(acc[0], a0, a1, a2, a3, Bf[k8][0][0], Bf[k8][0][1]);
                mma8(acc[1], a0, a1, a2, a3, Bf[k8][1][0], Bf[k8][1][1]);
            }
            const int rA = mt * 16 + g, rB = rA + 8;
#pragma unroll
            for (int nn = 0; nn < 2; ++nn) {
                const int c0 = n0 + nn * 8 + 2 * tg;
                const float b0v = bias[c0], b1v = bias[c0 + 1];
                if (rA < 66) {
                    float2 v = make_float2(acc[nn][0] + b0v, acc[nn][1] + b1v);
                    if (qkv && ((zlo && rA == 0) || (zhi && rA == 65))) v = make_float2(0.f, 0.f);
                    *(float2*)(O + rA * PST + c0) = v;
                }
                if (rB < 66) {
                    float2 v = make_float2(acc[nn][2] + b0v, acc[nn][3] + b1v);
                    if (qkv && ((zlo && rB == 0) || (zhi && rB == 65))) v = make_float2(0.f, 0.f);
                    *(float2*)(O + rB * PST + c0) = v;
                }
            }
        }
    }
    __syncthreads();

    // ---- transpose pw into WT slot 0 (tf32) ----
    for (int idx = tid; idx < 1024; idx += 640) {
        const int c = idx & 63, k4 = idx >> 6;
        const float4 w4 = *(const float4*)(pw + c * 64 + k4 * 4);
        float* dst = WT + c;
        dst[(4 * k4 + 0) * WST] = __uint_as_float(f2tf(w4.x));
        dst[(4 * k4 + 1) * WST] = __uint_as_float(f2tf(w4.y));
        dst[(4 * k4 + 2) * WST] = __uint_as_float(f2tf(w4.z));
        dst[(4 * k4 + 3) * WST] = __uint_as_float(f2tf(w4.w));
    }

    // ---- per-token stage with register-carried conv stencil ----
    // warp w<16: tokens jj in [1+3w, 1+3w+3); w>=16: [49+4(w-16), +4)  (jj=1..64)
    {
        const float* QP = PRE;
        const float* KP = PRE + PSLOT;
        const float* VP = PRE + 2 * PSLOT;
        const float* AP = PRE + 3 * PSLOT;
        const float* BP = PRE + 4 * PSLOT;
        const int s   = (warp < 16) ? (1 + 3 * warp) : (49 + 4 * (warp - 16));
        const int cnt = (warp < 16) ? 3 : 4;
        const int c0 = lane, c1 = lane + 32;

        // hoist conv weights/biases/gains
        float cwq[3][2], cwk[3][2], cwv[3][2];
#pragma unroll
        for (int tap = 0; tap < 3; ++tap) {
            cwq[tap][0] = CW[c0 * 3 + tap];        cwq[tap][1] = CW[c1 * 3 + tap];
            cwk[tap][0] = CW[192 + c0 * 3 + tap];  cwk[tap][1] = CW[192 + c1 * 3 + tap];
            cwv[tap][0] = CW[384 + c0 * 3 + tap];  cwv[tap][1] = CW[384 + c1 * 3 + tap];
        }
        const float cbq0 = CB[c0],        cbq1 = CB[c1];
        const float cbk0 = CB[64 + c0],   cbk1 = CB[64 + c1];
        const float cbv0 = CB[128 + c0],  cbv1 = CB[128 + c1];
        const float png0 = PNG[c0], png1 = PNG[c1];

        // carried stencil rows (preactivations), rows s-1 and s
        float qm[2], q0[2], km[2], k0[2], vm[2], v0[2];
#pragma unroll
        for (int h = 0; h < 2; ++h) {
            const int c = h ? c1 : c0;
            qm[h] = QP[(s - 1) * PST + c];  q0[h] = QP[s * PST + c];
            km[h] = KP[(s - 1) * PST + c];  k0[h] = KP[s * PST + c];
            vm[h] = VP[(s - 1) * PST + c];  v0[h] = VP[s * PST + c];
        }

        for (int t = s; t < s + cnt; ++t) {
            float qp[2], kp[2], vp[2], qv[2], kv[2], vv[2];
#pragma unroll
            for (int h = 0; h < 2; ++h) {
                const int c = h ? c1 : c0;
                qp[h] = QP[(t + 1) * PST + c];
                kp[h] = KP[(t + 1) * PST + c];
                vp[h] = VP[(t + 1) * PST + c];
                qv[h] = sigm(cwq[0][h] * qm[h] + cwq[1][h] * q0[h] + cwq[2][h] * qp[h] + (h ? cbq1 : cbq0));
                kv[h] = sigm(cwk[0][h] * km[h] + cwk[1][h] * k0[h] + cwk[2][h] * kp[h] + (h ? cbk1 : cbk0));
                vv[h] = sigm(cwv[0][h] * vm[h] + cwv[1][h] * v0[h] + cwv[2][h] * vp[h] + (h ? cbv1 : cbv0));
            }
            const float qi = rsqrtf(wredsum(qv[0] * qv[0] + qv[1] * qv[1]) + 1e-8f);
            const float ki = rsqrtf(wredsum(kv[0] * kv[0] + kv[1] * kv[1]) + 1e-8f);
            float d2[2];
#pragma unroll
            for (int h = 0; h < 2; ++h) {
                const int c = h ? c1 : c0;
                const float delta = (qv[h] * qi) * ((kv[h] * ki) * vv[h]);
                d2[h] = tanhf(AP[t * PST + c]) * delta + BP[t * PST + c];
            }
            const float mean = wredsum(d2[0] + d2[1]) * (1.0f / 64.0f);
            const float e0 = d2[0] - mean, e1 = d2[1] - mean;
            const float ms = wredsum(e0 * e0 + e1 * e1) * (1.0f / 64.0f);
            const float inv = rsqrtf(ms + 1e-8f);
            // write normalized delta (tf32) into HF fragments at token row t-1
            const int tk = t - 1;
            const int mt = tk >> 4, gd = tk & 7, hi = (tk >> 3) & 1;
            float* hf = HF + mt * TSLOT;
            hf[frag_off(gd, hi, c0)] = __uint_as_float(f2tf(e0 * inv * png0));
            hf[frag_off(gd, hi, c1)] = __uint_as_float(f2tf(e1 * inv * png1));
            // shift stencil
#pragma unroll
            for (int h = 0; h < 2; ++h) {
                qm[h] = q0[h]; q0[h] = qp[h];
                km[h] = k0[h]; k0[h] = kp[h];
                vm[h] = v0[h]; v0[h] = vp[h];
            }
        }
    }
    __syncthreads();

    // ---- final GEMM: 16 jobs m16 x n16 x k64, B(pw) hoisted, A from HF frags ----
    if (warp < 16) {
        const int mt = warp >> 2;
        const int n0 = (warp & 3) * 16;

        unsigned Bf[8][2][2];
#pragma unroll
        for (int k8 = 0; k8 < 8; ++k8) {
            const float* r0 = WT + (8 * k8 + tg) * WST + n0 + g;
            const float* r1 = r0 + 4 * WST;
            Bf[k8][0][0] = __float_as_uint(r0[0]);
            Bf[k8][0][1] = __float_as_uint(r1[0]);
            Bf[k8][1][0] = __float_as_uint(r0[8]);
            Bf[k8][1][1] = __float_as_uint(r1[8]);
        }

        const float4* Afp = (const float4*)(HF + mt * TSLOT);
        float acc[2][4];
#pragma unroll
        for (int i = 0; i < 2; ++i)
#pragma unroll
            for (int j = 0; j < 4; ++j) acc[i][j] = 0.f;

#pragma unroll
        for (int k8 = 0; k8 < 8; ++k8) {
            const float4 av = Afp[k8 * 33 + lane];
            mma8(acc[0], __float_as_uint(av.x), __float_as_uint(av.y),
                 __float_as_uint(av.z), __float_as_uint(av.w),
                 Bf[k8][0][0], Bf[k8][0][1]);
            mma8(acc[1], __float_as_uint(av.x), __float_as_uint(av.y),
                 __float_as_uint(av.z), __float_as_uint(av.w),
                 Bf[k8][1][0], Bf[k8][1][1]);
        }
#pragma unroll
        for (int nn = 0; nn < 2; ++nn) {
            const int col = n0 + nn * 8 + 2 * tg;
            const float pb0 = BIAS[320 + col], pb1 = BIAS[320 + col + 1];
#pragma unroll
            for (int h = 0; h < 2; ++h) {
                const int row = mt * 16 + g + 8 * h;     // token t0 + row
                const float d0 = acc[nn][2 * h + 0] + pb0;
                const float d1 = acc[nn][2 * h + 1] + pb1;
                const float g0 = sigm(d0 * sigm(d0));
                const float g1 = sigm(d1 * sigm(d1));
                const float2 xv = *(const float2*)(x + xbase + (long)row * 64 + col);
                float2 o = make_float2(xv.x + g0 * d0, xv.y + g1 * d1);
                *(float2*)(out + xbase + (long)row * 64 + col) = o;
            }
        }
    }
}

extern "C" void kernel_launch(void* const* d_in, const int* in_sizes, int n_in,
                              void* d_out, int out_size)
{
    const float* x      = (const float*)d_in[0];
    const float* norm_g = (const float*)d_in[1];
    const float* qw  = (const float*)d_in[2];
    const float* qb  = (const float*)d_in[3];
    const float* kw  = (const float*)d_in[4];
    const float* kb  = (const float*)d_in[5];
    const float* vw  = (const float*)d_in[6];
    const float* vb  = (const float*)d_in[7];
    const float* qcw = (const float*)d_in[8];
    const float* qcb = (const float*)d_in[9];
    const float* kcw = (const float*)d_in[10];
    const float* kcb = (const float*)d_in[11];
    const float* vcw = (const float*)d_in[12];
    const float* vcb = (const float*)d_in[13];
    const float* aw  = (const float*)d_in[14];
    const float* ab  = (const float*)d_in[15];
    const float* bw  = (const float*)d_in[16];
    const float* bb  = (const float*)d_in[17];
    const float* png = (const float*)d_in[18];
    const float* pw  = (const float*)d_in[19];
    const float* pb  = (const float*)d_in[20];
    float* out = (float*)d_out;

    const int smem_bytes = SMEM_FLOATS * (int)sizeof(float);
    cudaFuncSetAttribute(gdn_kernel, cudaFuncAttributeMaxDynamicSharedMemorySize, smem_bytes);
    gdn_kernel<<<4096, 640, smem_bytes>>>(
        x, norm_g, qw, qb, kw, kb, vw, vb, qcw, qcb, kcw, kcb, vcw, vcb,
        aw, ab, bw, bb, png, pw, pb, out);
}

// round 7
// speedup vs baseline: 1.2987x; 1.1200x over previous
#include <cuda_runtime.h>
#include <cuda_bf16.h>
#include <cstdint>

// B=64, T=4096, D=64. Token tile 64 (+2 halo rows), M padded to 80 (5 m16-tiles).
// 320 threads = 10 warps, 2 CTAs/SM (smem ~101KB, launch_bounds(320,2)).
// A operands in mma-fragment layout (FRK stride). B fragments LDG'd from global.
#define FRK 132
#define TSLOT (8 * FRK)    // 1056 floats per m16 tile
#define PST 68             // preactivation row stride (elements)

// shared memory byte offsets
#define OFF_XF   0                  // 5280 f  (x, tf32 bits, fragment layout)
#define OFF_HF   21120              // 5280 f  (h / delta-norm, tf32 bits, fragment)
#define OFF_BP   42240              // 4488 f  (b-linear preact, fp32)
#define OFF_QKVA 60192              // 4 x 4488 bf16 (q,k,v,a preacts)
#define OFF_BIAS 96096              // 384 f
#define OFF_CW   97632              // 576 f
#define OFF_CB   99936              // 192 f
#define OFF_NG   100704             // 64 f
#define OFF_PNG  100960             // 64 f
#define SMEM_BYTES 101216

__device__ __forceinline__ float sigm(float z) { return 1.0f / (1.0f + expf(-z)); }

__device__ __forceinline__ float wredsum(float v) {
#pragma unroll
    for (int o = 16; o; o >>= 1) v += __shfl_xor_sync(0xffffffffu, v, o);
    return v;
}

__device__ __forceinline__ unsigned f2tf(float f) {
    unsigned u;
    asm("cvt.rna.tf32.f32 %0, %1;" : "=r"(u) : "f"(f));
    return u;
}

// fragment scatter offset for value at (row-in-tile bits gd/hi, col c)
__device__ __forceinline__ int frag_off(int gd, int hi, int c) {
    return (c >> 3) * FRK + (4 * gd + (c & 3)) * 4 + hi + 2 * ((c >> 2) & 1);
}

__device__ __forceinline__ void mma8(float* d, unsigned a0, unsigned a1, unsigned a2, unsigned a3,
                                     unsigned b0, unsigned b1) {
    asm("mma.sync.aligned.m16n8k8.row.col.f32.tf32.tf32.f32 "
        "{%0,%1,%2,%3}, {%4,%5,%6,%7}, {%8,%9}, {%0,%1,%2,%3};"
        : "+f"(d[0]), "+f"(d[1]), "+f"(d[2]), "+f"(d[3])
        : "r"(a0), "r"(a1), "r"(a2), "r"(a3), "r"(b0), "r"(b1));
}

// Load a k64 x n16 B-fragment set from global W [64 out x 64 in], tf32-converted.
__device__ __forceinline__ void load_bfrag(const float* __restrict__ W, int n0, int g, int tg,
                                           unsigned Bf[8][2][2]) {
    const float* r0 = W + (n0 + g) * 64 + tg;
    const float* r1 = W + (n0 + g + 8) * 64 + tg;
#pragma unroll
    for (int k8 = 0; k8 < 8; ++k8) {
        Bf[k8][0][0] = f2tf(__ldg(r0 + 8 * k8));
        Bf[k8][0][1] = f2tf(__ldg(r0 + 8 * k8 + 4));
        Bf[k8][1][0] = f2tf(__ldg(r1 + 8 * k8));
        Bf[k8][1][1] = f2tf(__ldg(r1 + 8 * k8 + 4));
    }
}

__global__ void __launch_bounds__(320, 2) gdn_kernel(
    const float* __restrict__ x,   const float* __restrict__ norm_g,
    const float* __restrict__ qw,  const float* __restrict__ qb,
    const float* __restrict__ kw,  const float* __restrict__ kb,
    const float* __restrict__ vw,  const float* __restrict__ vb,
    const float* __restrict__ qcw, const float* __restrict__ qcb,
    const float* __restrict__ kcw, const float* __restrict__ kcb,
    const float* __restrict__ vcw, const float* __restrict__ vcb,
    const float* __restrict__ aw,  const float* __restrict__ ab,
    const float* __restrict__ bw,  const float* __restrict__ bb,
    const float* __restrict__ png, const float* __restrict__ pw,
    const float* __restrict__ pb,  float* __restrict__ out)
{
    extern __shared__ char smc[];
    float* XF   = (float*)(smc + OFF_XF);
    float* HF   = (float*)(smc + OFF_HF);
    float* BPf  = (float*)(smc + OFF_BP);
    __nv_bfloat16* QKVA = (__nv_bfloat16*)(smc + OFF_QKVA);
    float* BIAS = (float*)(smc + OFF_BIAS);
    float* CW   = (float*)(smc + OFF_CW);
    float* CB   = (float*)(smc + OFF_CB);
    float* NG   = (float*)(smc + OFF_NG);
    float* PNG  = (float*)(smc + OFF_PNG);

    const int tid  = threadIdx.x;
    const int warp = tid >> 5;
    const int lane = tid & 31;
    const int g    = lane >> 2;
    const int tg   = lane & 3;
    const int b    = blockIdx.x >> 6;
    const int t0   = (blockIdx.x & 63) << 6;
    const long xbase = ((long)b * 4096 + t0) * 64;
    const bool zlo = (t0 == 0), zhi = (t0 + 64 == 4096);

    // ---- small params ----
    if (tid < 64) {
        BIAS[tid]       = qb[tid];  BIAS[64 + tid]  = kb[tid];  BIAS[128 + tid] = vb[tid];
        BIAS[192 + tid] = ab[tid];  BIAS[256 + tid] = bb[tid];  BIAS[320 + tid] = pb[tid];
        CB[tid] = qcb[tid];  CB[64 + tid] = kcb[tid];  CB[128 + tid] = vcb[tid];
        NG[tid] = norm_g[tid];  PNG[tid] = png[tid];
    }
    if (tid >= 64 && tid < 256) {
        const int i = tid - 64;
        CW[i] = qcw[i]; CW[192 + i] = kcw[i]; CW[384 + i] = vcw[i];
    }
    __syncthreads();

    // ---- x load + zc_rmsnorm -> XF (x, tf32) and HF (h, tf32) fragments ----
    for (int r = warp; r < 80; r += 10) {
        const int gt = t0 - 1 + r;
        const bool valid = (r < 66) && (gt >= 0) && (gt < 4096);
        float a = 0.f, bv = 0.f;
        if (valid) {
            const float* xr = x + ((long)b * 4096 + gt) * 64;
            a  = xr[lane];
            bv = xr[lane + 32];
        }
        const int mt = r >> 4, gd = r & 7, hi = (r >> 3) & 1;
        const int o0 = frag_off(gd, hi, lane);
        const int o1 = frag_off(gd, hi, lane + 32);
        float* xf = XF + mt * TSLOT;
        float* hf = HF + mt * TSLOT;
        xf[o0] = __uint_as_float(f2tf(a));
        xf[o1] = __uint_as_float(f2tf(bv));
        const float mean = wredsum(a + bv) * (1.0f / 64.0f);
        const float am = a - mean, bm = bv - mean;
        const float ms = wredsum(am * am + bm * bm) * (1.0f / 64.0f);
        const float inv = rsqrtf(ms + 1e-8f);
        hf[o0] = __uint_as_float(f2tf(am * inv * NG[lane]));
        hf[o1] = __uint_as_float(f2tf(bm * inv * NG[lane + 32]));
    }
    __syncthreads();

    // ---- phase-1: 20 jobs = (matrix 0..4) x (n16 chunk 0..3); 2 jobs/warp ----
    {
        const float* wsrc[5] = { qw, kw, vw, aw, bw };
#pragma unroll
        for (int jj = 0; jj < 2; ++jj) {
            const int job = warp + 10 * jj;
            const int mat = job >> 2;          // 0..4
            const int n0  = (job & 3) * 16;
            const float* AF = (mat < 3) ? HF : XF;

            unsigned Bf[8][2][2];
            load_bfrag(wsrc[mat], n0, g, tg, Bf);

            const float* bias = BIAS + mat * 64;
            const bool qkv = (mat < 3);
            __nv_bfloat16* Ob = QKVA + mat * (66 * PST);   // valid for mat<4

#pragma unroll
            for (int mt = 0; mt < 5; ++mt) {
                const float4* Afp = (const float4*)(AF + mt * TSLOT);
                float acc[2][4];
#pragma unroll
                for (int i = 0; i < 2; ++i)
#pragma unroll
                    for (int j = 0; j < 4; ++j) acc[i][j] = 0.f;

#pragma unroll
                for (int k8 = 0; k8 < 8; ++k8) {
                    const float4 av = Afp[k8 * 33 + lane];
                    const unsigned a0 = __float_as_uint(av.x);
                    const unsigned a1 = __float_as_uint(av.y);
                    const unsigned a2 = __float_as_uint(av.z);
                    const unsigned a3 = __float_as_uint(av.w);
                    mma8(acc[0], a0, a1, a2, a3, Bf[k8][0][0], Bf[k8][0][1]);
                    mma8(acc[1], a0, a1, a2, a3, Bf[k8][1][0], Bf[k8][1][1]);
                }
                const int rA = mt * 16 + g, rB = rA + 8;
#pragma unroll
                for (int nn = 0; nn < 2; ++nn) {
                    const int c0 = n0 + nn * 8 + 2 * tg;
                    const float b0v = bias[c0], b1v = bias[c0 + 1];
#pragma unroll
                    for (int rr = 0; rr < 2; ++rr) {
                        const int r = rr ? rB : rA;
                        if (r >= 66) continue;
                        float v0 = acc[nn][2 * rr + 0] + b0v;
                        float v1 = acc[nn][2 * rr + 1] + b1v;
                        if (qkv && ((zlo && r == 0) || (zhi && r == 65))) { v0 = 0.f; v1 = 0.f; }
                        if (mat < 4) {
                            __nv_bfloat162 bv2;
                            bv2.x = __float2bfloat16(v0);
                            bv2.y = __float2bfloat16(v1);
                            *(__nv_bfloat162*)(Ob + r * PST + c0) = bv2;
                        } else {
                            *(float2*)(BPf + r * PST + c0) = make_float2(v0, v1);
                        }
                    }
                }
            }
        }
    }
    __syncthreads();

    // ---- per-token stage with register-carried conv stencil ----
    // warps 0..3: 7 tokens from s=1+7w; warps 4..9: 6 tokens from s=29+6(w-4)
    {
        const __nv_bfloat16* QP = QKVA;
        const __nv_bfloat16* KP = QKVA + 66 * PST;
        const __nv_bfloat16* VP = QKVA + 2 * 66 * PST;
        const __nv_bfloat16* AP = QKVA + 3 * 66 * PST;
        const int s   = (warp < 4) ? (1 + 7 * warp) : (29 + 6 * (warp - 4));
        const int cnt = (warp < 4) ? 7 : 6;
        const int c0 = lane, c1 = lane + 32;

        float cwq[3][2], cwk[3][2], cwv[3][2];
#pragma unroll
        for (int tap = 0; tap < 3; ++tap) {
            cwq[tap][0] = CW[c0 * 3 + tap];        cwq[tap][1] = CW[c1 * 3 + tap];
            cwk[tap][0] = CW[192 + c0 * 3 + tap];  cwk[tap][1] = CW[192 + c1 * 3 + tap];
            cwv[tap][0] = CW[384 + c0 * 3 + tap];  cwv[tap][1] = CW[384 + c1 * 3 + tap];
        }
        const float cbq0 = CB[c0],        cbq1 = CB[c1];
        const float cbk0 = CB[64 + c0],   cbk1 = CB[64 + c1];
        const float cbv0 = CB[128 + c0],  cbv1 = CB[128 + c1];
        const float png0 = PNG[c0], png1 = PNG[c1];

        float qm[2], q0[2], km[2], k0[2], vm[2], v0[2];
#pragma unroll
        for (int h = 0; h < 2; ++h) {
            const int c = h ? c1 : c0;
            qm[h] = __bfloat162float(QP[(s - 1) * PST + c]);
            q0[h] = __bfloat162float(QP[s * PST + c]);
            km[h] = __bfloat162float(KP[(s - 1) * PST + c]);
            k0[h] = __bfloat162float(KP[s * PST + c]);
            vm[h] = __bfloat162float(VP[(s - 1) * PST + c]);
            v0[h] = __bfloat162float(VP[s * PST + c]);
        }

        for (int t = s; t < s + cnt; ++t) {
            float qp[2], kp[2], vp[2], qv[2], kv[2], vv[2];
#pragma unroll
            for (int h = 0; h < 2; ++h) {
                const int c = h ? c1 : c0;
                qp[h] = __bfloat162float(QP[(t + 1) * PST + c]);
                kp[h] = __bfloat162float(KP[(t + 1) * PST + c]);
                vp[h] = __bfloat162float(VP[(t + 1) * PST + c]);
                qv[h] = sigm(cwq[0][h] * qm[h] + cwq[1][h] * q0[h] + cwq[2][h] * qp[h] + (h ? cbq1 : cbq0));
                kv[h] = sigm(cwk[0][h] * km[h] + cwk[1][h] * k0[h] + cwk[2][h] * kp[h] + (h ? cbk1 : cbk0));
                vv[h] = sigm(cwv[0][h] * vm[h] + cwv[1][h] * v0[h] + cwv[2][h] * vp[h] + (h ? cbv1 : cbv0));
            }
            const float qi = rsqrtf(wredsum(qv[0] * qv[0] + qv[1] * qv[1]) + 1e-8f);
            const float ki = rsqrtf(wredsum(kv[0] * kv[0] + kv[1] * kv[1]) + 1e-8f);
            float d2[2];
#pragma unroll
            for (int h = 0; h < 2; ++h) {
                const int c = h ? c1 : c0;
                const float delta = (qv[h] * qi) * ((kv[h] * ki) * vv[h]);
                const float av = __bfloat162float(AP[t * PST + c]);
                d2[h] = tanhf(av) * delta + BPf[t * PST + c];
            }
            const float mean = wredsum(d2[0] + d2[1]) * (1.0f / 64.0f);
            const float e0 = d2[0] - mean, e1 = d2[1] - mean;
            const float ms = wredsum(e0 * e0 + e1 * e1) * (1.0f / 64.0f);
            const float inv = rsqrtf(ms + 1e-8f);
            const int tk = t - 1;
            const int mt = tk >> 4, gd = tk & 7, hi = (tk >> 3) & 1;
            float* hf = HF + mt * TSLOT;
            hf[frag_off(gd, hi, c0)] = __uint_as_float(f2tf(e0 * inv * png0));
            hf[frag_off(gd, hi, c1)] = __uint_as_float(f2tf(e1 * inv * png1));
#pragma unroll
            for (int h = 0; h < 2; ++h) {
                qm[h] = q0[h]; q0[h] = qp[h];
                km[h] = k0[h]; k0[h] = kp[h];
                vm[h] = v0[h]; v0[h] = vp[h];
            }
        }
    }
    __syncthreads();

    // ---- final GEMM: 16 jobs m16 x n16 x k64; warps 0..5 do 2 jobs, 6..9 one ----
    for (int job = warp; job < 16; job += 10) {
        const int mt = job >> 2;
        const int n0 = (job & 3) * 16;

        unsigned Bf[8][2][2];
        load_bfrag(pw, n0, g, tg, Bf);

        const float4* Afp = (const float4*)(HF + mt * TSLOT);
        float acc[2][4];
#pragma unroll
        for (int i = 0; i < 2; ++i)
#pragma unroll
            for (int j = 0; j < 4; ++j) acc[i][j] = 0.f;

#pragma unroll
        for (int k8 = 0; k8 < 8; ++k8) {
            const float4 av = Afp[k8 * 33 + lane];
            mma8(acc[0], __float_as_uint(av.x), __float_as_uint(av.y),
                 __float_as_uint(av.z), __float_as_uint(av.w),
                 Bf[k8][0][0], Bf[k8][0][1]);
            mma8(acc[1], __float_as_uint(av.x), __float_as_uint(av.y),
                 __float_as_uint(av.z), __float_as_uint(av.w),
                 Bf[k8][1][0], Bf[k8][1][1]);
        }
#pragma unroll
        for (int nn = 0; nn < 2; ++nn) {
            const int col = n0 + nn * 8 + 2 * tg;
            const float pb0 = BIAS[320 + col], pb1 = BIAS[320 + col + 1];
#pragma unroll
            for (int h = 0; h < 2; ++h) {
                const int row = mt * 16 + g + 8 * h;     // token t0 + row
                const float d0 = acc[nn][2 * h + 0] + pb0;
                const float d1 = acc[nn][2 * h + 1] + pb1;
                const float g0 = sigm(d0 * sigm(d0));
                const float g1 = sigm(d1 * sigm(d1));
                const float2 xv = *(const float2*)(x + xbase + (long)row * 64 + col);
                float2 o = make_float2(xv.x + g0 * d0, xv.y + g1 * d1);
                *(float2*)(out + xbase + (long)row * 64 + col) = o;
            }
        }
    }
}

extern "C" void kernel_launch(void* const* d_in, const int* in_sizes, int n_in,
                              void* d_out, int out_size)
{
    const float* x      = (const float*)d_in[0];
    const float* norm_g = (const float*)d_in[1];
    const float* qw  = (const float*)d_in[2];
    const float* qb  = (const float*)d_in[3];
    const float* kw  = (const float*)d_in[4];
    const float* kb  = (const float*)d_in[5];
    const float* vw  = (const float*)d_in[6];
    const float* vb  = (const float*)d_in[7];
    const float* qcw = (const float*)d_in[8];
    const float* qcb = (const float*)d_in[9];
    const float* kcw = (const float*)d_in[10];
    const float* kcb = (const float*)d_in[11];
    const float* vcw = (const float*)d_in[12];
    const float* vcb = (const float*)d_in[13];
    const float* aw  = (const float*)d_in[14];
    const float* ab  = (const float*)d_in[15];
    const float* bw  = (const float*)d_in[16];
    const float* bb  = (const float*)d_in[17];
    const float* png = (const float*)d_in[18];
    const float* pw  = (const float*)d_in[19];
    const float* pb  = (const float*)d_in[20];
    float* out = (float*)d_out;

    cudaFuncSetAttribute(gdn_kernel, cudaFuncAttributeMaxDynamicSharedMemorySize, SMEM_BYTES);
    gdn_kernel<<<4096, 320, SMEM_BYTES>>>(
        x, norm_g, qw, qb, kw, kb, vw, vb, qcw, qcb, kcw, kcb, vcw, vcb,
        aw, ab, bw, bb, png, pw, pb, out);
}

// round 8
// speedup vs baseline: 1.6352x; 1.2591x over previous
#include <cuda_runtime.h>
#include <cuda_fp16.h>
#include <cstdint>

// B=64, T=4096, D=64. Token tile 64 (+2 halo rows), M padded to 80 (5 m16-tiles).
// 320 threads = 10 warps, 2 CTAs/SM.
// GEMMs: mma.sync m16n8k16 fp16 (fp32 accum). A operands in packed-half2 fragment
// layout: per m16-tile, 4 k16-chunks, each lane one float4 (=regs a0..a3), chunk
// stride 132 words (33 float4) for clean banking.
#define TSLOTW 528         // words (b32) per m16 tile: 4 chunks x 132
#define PST 68             // preactivation row stride (elements)

// shared memory byte offsets
#define OFF_XF   0                  // 10560 B (x, fp16 frags)
#define OFF_HF   10560              // 10560 B (h / delta-norm, fp16 frags)
#define OFF_BP   21120              // 17952 B (b-linear preact, fp32)
#define OFF_QKVA 39072              // 35904 B (4 x 66x68 fp16 preacts)
#define OFF_BIAS 74976              // 1536 B
#define OFF_CW   76512              // 2304 B
#define OFF_CB   78816              // 768 B
#define OFF_NG   79584              // 256 B
#define OFF_PNG  79840              // 256 B
#define SMEM_BYTES 80096

__device__ __forceinline__ float sigm(float z) { return 1.0f / (1.0f + expf(-z)); }

__device__ __forceinline__ float wredsum(float v) {
#pragma unroll
    for (int o = 16; o; o >>= 1) v += __shfl_xor_sync(0xffffffffu, v, o);
    return v;
}

// store one fp16 value into fragment layout at (row bits gd/hi, col c)
__device__ __forceinline__ void frag_store_h(float* tile, int gd, int hi, int c, float v) {
    const int cc = c & 15;
    const int word = (c >> 4) * 132 + (4 * gd + ((cc & 7) >> 1)) * 4 + hi + 2 * (cc >> 3);
    ((__half*)tile)[2 * word + (cc & 1)] = __float2half_rn(v);
}

__device__ __forceinline__ unsigned packh2(float lo, float hi) {
    __half2 h = __floats2half2_rn(lo, hi);
    return *(unsigned*)&h;
}

__device__ __forceinline__ void mma16(float* d, unsigned a0, unsigned a1, unsigned a2, unsigned a3,
                                      unsigned b0, unsigned b1) {
    asm("mma.sync.aligned.m16n8k16.row.col.f32.f16.f16.f32 "
        "{%0,%1,%2,%3}, {%4,%5,%6,%7}, {%8,%9}, {%0,%1,%2,%3};"
        : "+f"(d[0]), "+f"(d[1]), "+f"(d[2]), "+f"(d[3])
        : "r"(a0), "r"(a1), "r"(a2), "r"(a3), "r"(b0), "r"(b1));
}

// Load k64 x n16 B-fragments from global W [64 out x 64 in], fp16-packed.
// Bf[chunk][n8-half][reg]
__device__ __forceinline__ void load_bfrag(const float* __restrict__ W, int n0, int g, int tg,
                                           unsigned Bf[4][2][2]) {
    const float* r0 = W + (n0 + g) * 64 + 2 * tg;
    const float* r1 = W + (n0 + g + 8) * 64 + 2 * tg;
#pragma unroll
    for (int c = 0; c < 4; ++c) {
        const float2 v00 = *(const float2*)(r0 + 16 * c);
        const float2 v01 = *(const float2*)(r0 + 16 * c + 8);
        const float2 v10 = *(const float2*)(r1 + 16 * c);
        const float2 v11 = *(const float2*)(r1 + 16 * c + 8);
        Bf[c][0][0] = packh2(v00.x, v00.y);
        Bf[c][0][1] = packh2(v01.x, v01.y);
        Bf[c][1][0] = packh2(v10.x, v10.y);
        Bf[c][1][1] = packh2(v11.x, v11.y);
    }
}

__global__ void __launch_bounds__(320, 2) gdn_kernel(
    const float* __restrict__ x,   const float* __restrict__ norm_g,
    const float* __restrict__ qw,  const float* __restrict__ qb,
    const float* __restrict__ kw,  const float* __restrict__ kb,
    const float* __restrict__ vw,  const float* __restrict__ vb,
    const float* __restrict__ qcw, const float* __restrict__ qcb,
    const float* __restrict__ kcw, const float* __restrict__ kcb,
    const float* __restrict__ vcw, const float* __restrict__ vcb,
    const float* __restrict__ aw,  const float* __restrict__ ab,
    const float* __restrict__ bw,  const float* __restrict__ bb,
    const float* __restrict__ png, const float* __restrict__ pw,
    const float* __restrict__ pb,  float* __restrict__ out)
{
    extern __shared__ char smc[];
    float* XF   = (float*)(smc + OFF_XF);
    float* HF   = (float*)(smc + OFF_HF);
    float* BPf  = (float*)(smc + OFF_BP);
    __half* QKVA = (__half*)(smc + OFF_QKVA);
    float* BIAS = (float*)(smc + OFF_BIAS);
    float* CW   = (float*)(smc + OFF_CW);
    float* CB   = (float*)(smc + OFF_CB);
    float* NG   = (float*)(smc + OFF_NG);
    float* PNG  = (float*)(smc + OFF_PNG);

    const int tid  = threadIdx.x;
    const int warp = tid >> 5;
    const int lane = tid & 31;
    const int g    = lane >> 2;
    const int tg   = lane & 3;
    const int b    = blockIdx.x >> 6;
    const int t0   = (blockIdx.x & 63) << 6;
    const long xbase = ((long)b * 4096 + t0) * 64;
    const bool zlo = (t0 == 0), zhi = (t0 + 64 == 4096);

    // ---- small params ----
    if (tid < 64) {
        BIAS[tid]       = qb[tid];  BIAS[64 + tid]  = kb[tid];  BIAS[128 + tid] = vb[tid];
        BIAS[192 + tid] = ab[tid];  BIAS[256 + tid] = bb[tid];  BIAS[320 + tid] = pb[tid];
        CB[tid] = qcb[tid];  CB[64 + tid] = kcb[tid];  CB[128 + tid] = vcb[tid];
        NG[tid] = norm_g[tid];  PNG[tid] = png[tid];
    }
    if (tid >= 64 && tid < 256) {
        const int i = tid - 64;
        CW[i] = qcw[i]; CW[192 + i] = kcw[i]; CW[384 + i] = vcw[i];
    }
    __syncthreads();

    // ---- x load + zc_rmsnorm -> XF (x fp16 frags) and HF (h fp16 frags) ----
    for (int r = warp; r < 80; r += 10) {
        const int gt = t0 - 1 + r;
        const bool valid = (r < 66) && (gt >= 0) && (gt < 4096);
        float a = 0.f, bv = 0.f;
        if (valid) {
            const float* xr = x + ((long)b * 4096 + gt) * 64;
            a  = xr[lane];
            bv = xr[lane + 32];
        }
        const int mt = r >> 4, gd = r & 7, hi = (r >> 3) & 1;
        float* xf = XF + mt * TSLOTW;
        float* hf = HF + mt * TSLOTW;
        frag_store_h(xf, gd, hi, lane, a);
        frag_store_h(xf, gd, hi, lane + 32, bv);
        const float mean = wredsum(a + bv) * (1.0f / 64.0f);
        const float am = a - mean, bm = bv - mean;
        const float ms = wredsum(am * am + bm * bm) * (1.0f / 64.0f);
        const float inv = rsqrtf(ms + 1e-8f);
        frag_store_h(hf, gd, hi, lane,      am * inv * NG[lane]);
        frag_store_h(hf, gd, hi, lane + 32, bm * inv * NG[lane + 32]);
    }
    __syncthreads();

    // ---- phase-1: 20 jobs = (matrix 0..4) x (n16 chunk 0..3); 2 jobs/warp ----
    {
        const float* wsrc[5] = { qw, kw, vw, aw, bw };
#pragma unroll
        for (int jj = 0; jj < 2; ++jj) {
            const int job = warp + 10 * jj;
            const int mat = job >> 2;          // 0..4
            const int n0  = (job & 3) * 16;
            const float* AF = (mat < 3) ? HF : XF;

            unsigned Bf[4][2][2];
            load_bfrag(wsrc[mat], n0, g, tg, Bf);

            const float* bias = BIAS + mat * 64;
            const bool qkv = (mat < 3);
            __half* Ob = QKVA + mat * (66 * PST);   // valid for mat<4

#pragma unroll
            for (int mt = 0; mt < 5; ++mt) {
                const float4* Afp = (const float4*)(AF + mt * TSLOTW);
                float acc[2][4];
#pragma unroll
                for (int i = 0; i < 2; ++i)
#pragma unroll
                    for (int j = 0; j < 4; ++j) acc[i][j] = 0.f;

#pragma unroll
                for (int c = 0; c < 4; ++c) {
                    const float4 av = Afp[c * 33 + lane];
                    const unsigned a0 = __float_as_uint(av.x);
                    const unsigned a1 = __float_as_uint(av.y);
                    const unsigned a2 = __float_as_uint(av.z);
                    const unsigned a3 = __float_as_uint(av.w);
                    mma16(acc[0], a0, a1, a2, a3, Bf[c][0][0], Bf[c][0][1]);
                    mma16(acc[1], a0, a1, a2, a3, Bf[c][1][0], Bf[c][1][1]);
                }
                const int rA = mt * 16 + g, rB = rA + 8;
#pragma unroll
                for (int nn = 0; nn < 2; ++nn) {
                    const int c0 = n0 + nn * 8 + 2 * tg;
                    const float b0v = bias[c0], b1v = bias[c0 + 1];
#pragma unroll
                    for (int rr = 0; rr < 2; ++rr) {
                        const int r = rr ? rB : rA;
                        if (r >= 66) continue;
                        float v0 = acc[nn][2 * rr + 0] + b0v;
                        float v1 = acc[nn][2 * rr + 1] + b1v;
                        if (qkv && ((zlo && r == 0) || (zhi && r == 65))) { v0 = 0.f; v1 = 0.f; }
                        if (mat < 4) {
                            *(__half2*)(Ob + r * PST + c0) = __floats2half2_rn(v0, v1);
                        } else {
                            *(float2*)(BPf + r * PST + c0) = make_float2(v0, v1);
                        }
                    }
                }
            }
        }
    }
    __syncthreads();

    // ---- per-token stage with register-carried conv stencil ----
    // warps 0..3: 7 tokens from s=1+7w; warps 4..9: 6 tokens from s=29+6(w-4)
    {
        const __half* QP = QKVA;
        const __half* KP = QKVA + 66 * PST;
        const __half* VP = QKVA + 2 * 66 * PST;
        const __half* AP = QKVA + 3 * 66 * PST;
        const int s   = (warp < 4) ? (1 + 7 * warp) : (29 + 6 * (warp - 4));
        const int cnt = (warp < 4) ? 7 : 6;
        const int c0 = lane, c1 = lane + 32;

        float cwq[3][2], cwk[3][2], cwv[3][2];
#pragma unroll
        for (int tap = 0; tap < 3; ++tap) {
            cwq[tap][0] = CW[c0 * 3 + tap];        cwq[tap][1] = CW[c1 * 3 + tap];
            cwk[tap][0] = CW[192 + c0 * 3 + tap];  cwk[tap][1] = CW[192 + c1 * 3 + tap];
            cwv[tap][0] = CW[384 + c0 * 3 + tap];  cwv[tap][1] = CW[384 + c1 * 3 + tap];
        }
        const float cbq0 = CB[c0],        cbq1 = CB[c1];
        const float cbk0 = CB[64 + c0],   cbk1 = CB[64 + c1];
        const float cbv0 = CB[128 + c0],  cbv1 = CB[128 + c1];
        const float png0 = PNG[c0], png1 = PNG[c1];

        float qm[2], q0[2], km[2], k0[2], vm[2], v0[2];
#pragma unroll
        for (int h = 0; h < 2; ++h) {
            const int c = h ? c1 : c0;
            qm[h] = __half2float(QP[(s - 1) * PST + c]);
            q0[h] = __half2float(QP[s * PST + c]);
            km[h] = __half2float(KP[(s - 1) * PST + c]);
            k0[h] = __half2float(KP[s * PST + c]);
            vm[h] = __half2float(VP[(s - 1) * PST + c]);
            v0[h] = __half2float(VP[s * PST + c]);
        }

        for (int t = s; t < s + cnt; ++t) {
            float qp[2], kp[2], vp[2], qv[2], kv[2], vv[2];
#pragma unroll
            for (int h = 0; h < 2; ++h) {
                const int c = h ? c1 : c0;
                qp[h] = __half2float(QP[(t + 1) * PST + c]);
                kp[h] = __half2float(KP[(t + 1) * PST + c]);
                vp[h] = __half2float(VP[(t + 1) * PST + c]);
                qv[h] = sigm(cwq[0][h] * qm[h] + cwq[1][h] * q0[h] + cwq[2][h] * qp[h] + (h ? cbq1 : cbq0));
                kv[h] = sigm(cwk[0][h] * km[h] + cwk[1][h] * k0[h] + cwk[2][h] * kp[h] + (h ? cbk1 : cbk0));
                vv[h] = sigm(cwv[0][h] * vm[h] + cwv[1][h] * v0[h] + cwv[2][h] * vp[h] + (h ? cbv1 : cbv0));
            }
            const float qi = rsqrtf(wredsum(qv[0] * qv[0] + qv[1] * qv[1]) + 1e-8f);
            const float ki = rsqrtf(wredsum(kv[0] * kv[0] + kv[1] * kv[1]) + 1e-8f);
            float d2[2];
#pragma unroll
            for (int h = 0; h < 2; ++h) {
                const int c = h ? c1 : c0;
                const float delta = (qv[h] * qi) * ((kv[h] * ki) * vv[h]);
                const float av = __half2float(AP[t * PST + c]);
                d2[h] = tanhf(av) * delta + BPf[t * PST + c];
            }
            const float mean = wredsum(d2[0] + d2[1]) * (1.0f / 64.0f);
            const float e0 = d2[0] - mean, e1 = d2[1] - mean;
            const float ms = wredsum(e0 * e0 + e1 * e1) * (1.0f / 64.0f);
            const float inv = rsqrtf(ms + 1e-8f);
            const int tk = t - 1;
            const int mt = tk >> 4, gd = tk & 7, hi = (tk >> 3) & 1;
            float* hf = HF + mt * TSLOTW;
            frag_store_h(hf, gd, hi, c0, e0 * inv * png0);
            frag_store_h(hf, gd, hi, c1, e1 * inv * png1);
#pragma unroll
            for (int h = 0; h < 2; ++h) {
                qm[h] = q0[h]; q0[h] = qp[h];
                km[h] = k0[h]; k0[h] = kp[h];
                vm[h] = v0[h]; v0[h] = vp[h];
            }
        }
    }
    __syncthreads();

    // ---- final GEMM: 16 jobs m16 x n16 x k64; warps 0..5 do 2 jobs, 6..9 one ----
    for (int job = warp; job < 16; job += 10) {
        const int mt = job >> 2;
        const int n0 = (job & 3) * 16;

        unsigned Bf[4][2][2];
        load_bfrag(pw, n0, g, tg, Bf);

        const float4* Afp = (const float4*)(HF + mt * TSLOTW);
        float acc[2][4];
#pragma unroll
        for (int i = 0; i < 2; ++i)
#pragma unroll
            for (int j = 0; j < 4; ++j) acc[i][j] = 0.f;

#pragma unroll
        for (int c = 0; c < 4; ++c) {
            const float4 av = Afp[c * 33 + lane];
            mma16(acc[0], __float_as_uint(av.x), __float_as_uint(av.y),
                  __float_as_uint(av.z), __float_as_uint(av.w),
                  Bf[c][0][0], Bf[c][0][1]);
            mma16(acc[1], __float_as_uint(av.x), __float_as_uint(av.y),
                  __float_as_uint(av.z), __float_as_uint(av.w),
                  Bf[c][1][0], Bf[c][1][1]);
        }
#pragma unroll
        for (int nn = 0; nn < 2; ++nn) {
            const int col = n0 + nn * 8 + 2 * tg;
            const float pb0 = BIAS[320 + col], pb1 = BIAS[320 + col + 1];
#pragma unroll
            for (int h = 0; h < 2; ++h) {
                const int row = mt * 16 + g + 8 * h;     // token t0 + row
                const float d0 = acc[nn][2 * h + 0] + pb0;
                const float d1 = acc[nn][2 * h + 1] + pb1;
                const float g0 = sigm(d0 * sigm(d0));
                const float g1 = sigm(d1 * sigm(d1));
                const float2 xv = *(const float2*)(x + xbase + (long)row * 64 + col);
                float2 o = make_float2(xv.x + g0 * d0, xv.y + g1 * d1);
                *(float2*)(out + xbase + (long)row * 64 + col) = o;
            }
        }
    }
}

extern "C" void kernel_launch(void* const* d_in, const int* in_sizes, int n_in,
                              void* d_out, int out_size)
{
    const float* x      = (const float*)d_in[0];
    const float* norm_g = (const float*)d_in[1];
    const float* qw  = (const float*)d_in[2];
    const float* qb  = (const float*)d_in[3];
    const float* kw  = (const float*)d_in[4];
    const float* kb  = (const float*)d_in[5];
    const float* vw  = (const float*)d_in[6];
    const float* vb  = (const float*)d_in[7];
    const float* qcw = (const float*)d_in[8];
    const float* qcb = (const float*)d_in[9];
    const float* kcw = (const float*)d_in[10];
    const float* kcb = (const float*)d_in[11];
    const float* vcw = (const float*)d_in[12];
    const float* vcb = (const float*)d_in[13];
    const float* aw  = (const float*)d_in[14];
    const float* ab  = (const float*)d_in[15];
    const float* bw  = (const float*)d_in[16];
    const float* bb  = (const float*)d_in[17];
    const float* png = (const float*)d_in[18];
    const float* pw  = (const float*)d_in[19];
    const float* pb  = (const float*)d_in[20];
    float* out = (float*)d_out;

    cudaFuncSetAttribute(gdn_kernel, cudaFuncAttributeMaxDynamicSharedMemorySize, SMEM_BYTES);
    gdn_kernel<<<4096, 320, SMEM_BYTES>>>(
        x, norm_g, qw, qb, kw, kb, vw, vb, qcw, qcb, kcw, kcb, vcw, vcb,
        aw, ab, bw, bb, png, pw, pb, out);
}

// round 9
// speedup vs baseline: 2.1049x; 1.2872x over previous
#include <cuda_runtime.h>
#include <cuda_fp16.h>
#include <cstdint>

// B=64, T=4096, D=64. Token tile 64 (+2 halo rows), M padded to 80 (5 m16-tiles).
// 320 threads = 10 warps, 2 CTAs/SM.
// GEMMs: mma.sync m16n8k16 fp16 (fp32 accum). A operands in packed-half2 fragment
// layout: per m16-tile, 4 k16-chunks, each lane one float4, chunk stride 132 words.
#define TSLOTW 528         // words (b32) per m16 tile: 4 chunks x 132
#define PST 68             // preactivation row stride (elements)

// shared memory byte offsets
#define OFF_XF   0                  // 10560 B (x, fp16 frags)
#define OFF_HF   10560              // 10560 B (h / delta-norm, fp16 frags)
#define OFF_BP   21120              // 17952 B (b-linear preact, fp32)
#define OFF_QKVA 39072              // 35904 B (4 x 66x68 fp16 preacts)
#define OFF_BIAS 74976              // 1536 B
#define OFF_CW   76512              // 2304 B
#define OFF_CB   78816              // 768 B
#define OFF_NG   79584              // 256 B
#define OFF_PNG  79840              // 256 B
#define SMEM_BYTES 80096

// fast sigmoid / tanh (MUFU-based; |args| here are O(1..10), no overflow risk)
__device__ __forceinline__ float sigm(float z) {
    return __fdividef(1.0f, 1.0f + __expf(-z));
}
__device__ __forceinline__ float tanh_fast(float a) {
    const float t = __expf(2.0f * a);
    return __fdividef(t - 1.0f, t + 1.0f);
}

// interleaved 2-value butterfly reduction (one latency chain for two sums)
__device__ __forceinline__ void wredsum2(float& a, float& b) {
#pragma unroll
    for (int o = 16; o; o >>= 1) {
        a += __shfl_xor_sync(0xffffffffu, a, o);
        b += __shfl_xor_sync(0xffffffffu, b, o);
    }
}

__device__ __forceinline__ unsigned packh2(float lo, float hi) {
    __half2 h = __floats2half2_rn(lo, hi);
    return *(unsigned*)&h;
}

// store packed half2 for adjacent cols (2*lane, 2*lane+1) at row bits gd/hi
__device__ __forceinline__ void frag_store_w(float* tile, int gd, int hi, int lane, unsigned w) {
    const int c = 2 * lane;
    const int cc = c & 15;
    const int word = (c >> 4) * 132 + (4 * gd + ((cc & 7) >> 1)) * 4 + hi + 2 * (cc >> 3);
    ((unsigned*)tile)[word] = w;
}

__device__ __forceinline__ void mma16(float* d, unsigned a0, unsigned a1, unsigned a2, unsigned a3,
                                      unsigned b0, unsigned b1) {
    asm("mma.sync.aligned.m16n8k16.row.col.f32.f16.f16.f32 "
        "{%0,%1,%2,%3}, {%4,%5,%6,%7}, {%8,%9}, {%0,%1,%2,%3};"
        : "+f"(d[0]), "+f"(d[1]), "+f"(d[2]), "+f"(d[3])
        : "r"(a0), "r"(a1), "r"(a2), "r"(a3), "r"(b0), "r"(b1));
}

// Load k64 x n16 B-fragments from global W [64 out x 64 in], fp16-packed.
__device__ __forceinline__ void load_bfrag(const float* __restrict__ W, int n0, int g, int tg,
                                           unsigned Bf[4][2][2]) {
    const float* r0 = W + (n0 + g) * 64 + 2 * tg;
    const float* r1 = W + (n0 + g + 8) * 64 + 2 * tg;
#pragma unroll
    for (int c = 0; c < 4; ++c) {
        const float2 v00 = *(const float2*)(r0 + 16 * c);
        const float2 v01 = *(const float2*)(r0 + 16 * c + 8);
        const float2 v10 = *(const float2*)(r1 + 16 * c);
        const float2 v11 = *(const float2*)(r1 + 16 * c + 8);
        Bf[c][0][0] = packh2(v00.x, v00.y);
        Bf[c][0][1] = packh2(v01.x, v01.y);
        Bf[c][1][0] = packh2(v10.x, v10.y);
        Bf[c][1][1] = packh2(v11.x, v11.y);
    }
}

__global__ void __launch_bounds__(320, 2) gdn_kernel(
    const float* __restrict__ x,   const float* __restrict__ norm_g,
    const float* __restrict__ qw,  const float* __restrict__ qb,
    const float* __restrict__ kw,  const float* __restrict__ kb,
    const float* __restrict__ vw,  const float* __restrict__ vb,
    const float* __restrict__ qcw, const float* __restrict__ qcb,
    const float* __restrict__ kcw, const float* __restrict__ kcb,
    const float* __restrict__ vcw, const float* __restrict__ vcb,
    const float* __restrict__ aw,  const float* __restrict__ ab,
    const float* __restrict__ bw,  const float* __restrict__ bb,
    const float* __restrict__ png, const float* __restrict__ pw,
    const float* __restrict__ pb,  float* __restrict__ out)
{
    extern __shared__ char smc[];
    float* XF   = (float*)(smc + OFF_XF);
    float* HF   = (float*)(smc + OFF_HF);
    float* BPf  = (float*)(smc + OFF_BP);
    __half* QKVA = (__half*)(smc + OFF_QKVA);
    float* BIAS = (float*)(smc + OFF_BIAS);
    float* CW   = (float*)(smc + OFF_CW);
    float* CB   = (float*)(smc + OFF_CB);
    float* NG   = (float*)(smc + OFF_NG);
    float* PNG  = (float*)(smc + OFF_PNG);

    const int tid  = threadIdx.x;
    const int warp = tid >> 5;
    const int lane = tid & 31;
    const int g    = lane >> 2;
    const int tg   = lane & 3;
    const int b    = blockIdx.x >> 6;
    const int t0   = (blockIdx.x & 63) << 6;
    const long xbase = ((long)b * 4096 + t0) * 64;
    const bool zlo = (t0 == 0), zhi = (t0 + 64 == 4096);

    // ---- small params ----
    if (tid < 64) {
        BIAS[tid]       = qb[tid];  BIAS[64 + tid]  = kb[tid];  BIAS[128 + tid] = vb[tid];
        BIAS[192 + tid] = ab[tid];  BIAS[256 + tid] = bb[tid];  BIAS[320 + tid] = pb[tid];
        CB[tid] = qcb[tid];  CB[64 + tid] = kcb[tid];  CB[128 + tid] = vcb[tid];
        NG[tid] = norm_g[tid];  PNG[tid] = png[tid];
    }
    if (tid >= 64 && tid < 256) {
        const int i = tid - 64;
        CW[i] = qcw[i]; CW[192 + i] = kcw[i]; CW[384 + i] = vcw[i];
    }
    __syncthreads();

    // ---- x load + zc_rmsnorm -> XF/HF fp16 frags; channels (2*lane, 2*lane+1) ----
    {
        const float2 ng2 = *(const float2*)(NG + 2 * lane);
        for (int r = warp; r < 80; r += 10) {
            const int gt = t0 - 1 + r;
            const bool valid = (r < 66) && (gt >= 0) && (gt < 4096);
            float a = 0.f, bv = 0.f;
            if (valid) {
                const float2 xv = *(const float2*)(x + ((long)b * 4096 + gt) * 64 + 2 * lane);
                a = xv.x; bv = xv.y;
            }
            const int mt = r >> 4, gd = r & 7, hi = (r >> 3) & 1;
            frag_store_w(XF + mt * TSLOTW, gd, hi, lane, packh2(a, bv));
            float s1 = a + bv, s2 = a * a + bv * bv;
            wredsum2(s1, s2);
            const float mean = s1 * (1.0f / 64.0f);
            const float var  = s2 * (1.0f / 64.0f) - mean * mean;
            const float inv  = rsqrtf(var + 1e-8f);
            frag_store_w(HF + mt * TSLOTW, gd, hi, lane,
                         packh2((a - mean) * inv * ng2.x, (bv - mean) * inv * ng2.y));
        }
    }
    __syncthreads();

    // ---- phase-1: 20 jobs = (matrix 0..4) x (n16 chunk 0..3); 2 jobs/warp ----
    {
        const float* wsrc[5] = { qw, kw, vw, aw, bw };
#pragma unroll
        for (int jj = 0; jj < 2; ++jj) {
            const int job = warp + 10 * jj;
            const int mat = job >> 2;          // 0..4
            const int n0  = (job & 3) * 16;
            const float* AF = (mat < 3) ? HF : XF;

            unsigned Bf[4][2][2];
            load_bfrag(wsrc[mat], n0, g, tg, Bf);

            const float* bias = BIAS + mat * 64;
            const bool qkv = (mat < 3);
            __half* Ob = QKVA + mat * (66 * PST);   // valid for mat<4

#pragma unroll
            for (int mt = 0; mt < 5; ++mt) {
                const float4* Afp = (const float4*)(AF + mt * TSLOTW);
                float acc[2][4];
#pragma unroll
                for (int i = 0; i < 2; ++i)
#pragma unroll
                    for (int j = 0; j < 4; ++j) acc[i][j] = 0.f;

#pragma unroll
                for (int c = 0; c < 4; ++c) {
                    const float4 av = Afp[c * 33 + lane];
                    const unsigned a0 = __float_as_uint(av.x);
                    const unsigned a1 = __float_as_uint(av.y);
                    const unsigned a2 = __float_as_uint(av.z);
                    const unsigned a3 = __float_as_uint(av.w);
                    mma16(acc[0], a0, a1, a2, a3, Bf[c][0][0], Bf[c][0][1]);
                    mma16(acc[1], a0, a1, a2, a3, Bf[c][1][0], Bf[c][1][1]);
                }
                const int rA = mt * 16 + g, rB = rA + 8;
#pragma unroll
                for (int nn = 0; nn < 2; ++nn) {
                    const int c0 = n0 + nn * 8 + 2 * tg;
                    const float b0v = bias[c0], b1v = bias[c0 + 1];
#pragma unroll
                    for (int rr = 0; rr < 2; ++rr) {
                        const int r = rr ? rB : rA;
                        if (r >= 66) continue;
                        float v0 = acc[nn][2 * rr + 0] + b0v;
                        float v1 = acc[nn][2 * rr + 1] + b1v;
                        if (qkv && ((zlo && r == 0) || (zhi && r == 65))) { v0 = 0.f; v1 = 0.f; }
                        if (mat < 4) {
                            *(__half2*)(Ob + r * PST + c0) = __floats2half2_rn(v0, v1);
                        } else {
                            *(float2*)(BPf + r * PST + c0) = make_float2(v0, v1);
                        }
                    }
                }
            }
        }
    }
    __syncthreads();

    // ---- per-token stage; channels (2*lane, 2*lane+1), register-carried stencil ----
    // warps 0..3: 7 tokens from s=1+7w; warps 4..9: 6 tokens from s=29+6(w-4)
    {
        const __half* QP = QKVA;
        const __half* KP = QKVA + 66 * PST;
        const __half* VP = QKVA + 2 * 66 * PST;
        const __half* AP = QKVA + 3 * 66 * PST;
        const int s   = (warp < 4) ? (1 + 7 * warp) : (29 + 6 * (warp - 4));
        const int cnt = (warp < 4) ? 7 : 6;
        const int cc0 = 2 * lane;

        float cwq[3][2], cwk[3][2], cwv[3][2];
#pragma unroll
        for (int tap = 0; tap < 3; ++tap) {
            cwq[tap][0] = CW[cc0 * 3 + tap];        cwq[tap][1] = CW[(cc0 + 1) * 3 + tap];
            cwk[tap][0] = CW[192 + cc0 * 3 + tap];  cwk[tap][1] = CW[192 + (cc0 + 1) * 3 + tap];
            cwv[tap][0] = CW[384 + cc0 * 3 + tap];  cwv[tap][1] = CW[384 + (cc0 + 1) * 3 + tap];
        }
        const float2 cbq = *(const float2*)(CB + cc0);
        const float2 cbk = *(const float2*)(CB + 64 + cc0);
        const float2 cbv = *(const float2*)(CB + 128 + cc0);
        const float2 pg2 = *(const float2*)(PNG + cc0);

        float qm[2], q0[2], km[2], k0[2], vm[2], v0[2];
        {
            const float2 qa = __half22float2(*(const __half2*)(QP + (s - 1) * PST + cc0));
            const float2 qbv = __half22float2(*(const __half2*)(QP + s * PST + cc0));
            const float2 ka = __half22float2(*(const __half2*)(KP + (s - 1) * PST + cc0));
            const float2 kbv = __half22float2(*(const __half2*)(KP + s * PST + cc0));
            const float2 va = __half22float2(*(const __half2*)(VP + (s - 1) * PST + cc0));
            const float2 vbv = __half22float2(*(const __half2*)(VP + s * PST + cc0));
            qm[0] = qa.x; qm[1] = qa.y; q0[0] = qbv.x; q0[1] = qbv.y;
            km[0] = ka.x; km[1] = ka.y; k0[0] = kbv.x; k0[1] = kbv.y;
            vm[0] = va.x; vm[1] = va.y; v0[0] = vbv.x; v0[1] = vbv.y;
        }

        for (int t = s; t < s + cnt; ++t) {
            const float2 qpv = __half22float2(*(const __half2*)(QP + (t + 1) * PST + cc0));
            const float2 kpv = __half22float2(*(const __half2*)(KP + (t + 1) * PST + cc0));
            const float2 vpv = __half22float2(*(const __half2*)(VP + (t + 1) * PST + cc0));
            const float qp[2] = { qpv.x, qpv.y };
            const float kp[2] = { kpv.x, kpv.y };
            const float vp[2] = { vpv.x, vpv.y };
            float qv[2], kv[2], vv[2];
#pragma unroll
            for (int h = 0; h < 2; ++h) {
                qv[h] = sigm(cwq[0][h] * qm[h] + cwq[1][h] * q0[h] + cwq[2][h] * qp[h] + (h ? cbq.y : cbq.x));
                kv[h] = sigm(cwk[0][h] * km[h] + cwk[1][h] * k0[h] + cwk[2][h] * kp[h] + (h ? cbk.y : cbk.x));
                vv[h] = sigm(cwv[0][h] * vm[h] + cwv[1][h] * v0[h] + cwv[2][h] * vp[h] + (h ? cbv.y : cbv.x));
            }
            float qs = qv[0] * qv[0] + qv[1] * qv[1];
            float ks = kv[0] * kv[0] + kv[1] * kv[1];
            wredsum2(qs, ks);
            const float qi = rsqrtf(qs + 1e-8f);
            const float ki = rsqrtf(ks + 1e-8f);
            const float2 av2 = __half22float2(*(const __half2*)(AP + t * PST + cc0));
            const float2 bp2 = *(const float2*)(BPf + t * PST + cc0);
            float d2[2];
            d2[0] = tanh_fast(av2.x) * ((qv[0] * qi) * ((kv[0] * ki) * vv[0])) + bp2.x;
            d2[1] = tanh_fast(av2.y) * ((qv[1] * qi) * ((kv[1] * ki) * vv[1])) + bp2.y;
            float s1 = d2[0] + d2[1], s2 = d2[0] * d2[0] + d2[1] * d2[1];
            wredsum2(s1, s2);
            const float mean = s1 * (1.0f / 64.0f);
            const float var  = s2 * (1.0f / 64.0f) - mean * mean;
            const float inv  = rsqrtf(var + 1e-8f);
            const int tk = t - 1;
            const int mt = tk >> 4, gd = tk & 7, hi = (tk >> 3) & 1;
            frag_store_w(HF + mt * TSLOTW, gd, hi, lane,
                         packh2((d2[0] - mean) * inv * pg2.x, (d2[1] - mean) * inv * pg2.y));
#pragma unroll
            for (int h = 0; h < 2; ++h) {
                qm[h] = q0[h]; q0[h] = qp[h];
                km[h] = k0[h]; k0[h] = kp[h];
                vm[h] = v0[h]; v0[h] = vp[h];
            }
        }
    }
    __syncthreads();

    // ---- final GEMM: 16 jobs m16 x n16 x k64; warps 0..5 do 2 jobs, 6..9 one ----
    for (int job = warp; job < 16; job += 10) {
        const int mt = job >> 2;
        const int n0 = (job & 3) * 16;

        unsigned Bf[4][2][2];
        load_bfrag(pw, n0, g, tg, Bf);

        const float4* Afp = (const float4*)(HF + mt * TSLOTW);
        float acc[2][4];
#pragma unroll
        for (int i = 0; i < 2; ++i)
#pragma unroll
            for (int j = 0; j < 4; ++j) acc[i][j] = 0.f;

#pragma unroll
        for (int c = 0; c < 4; ++c) {
            const float4 av = Afp[c * 33 + lane];
            mma16(acc[0], __float_as_uint(av.x), __float_as_uint(av.y),
                  __float_as_uint(av.z), __float_as_uint(av.w),
                  Bf[c][0][0], Bf[c][0][1]);
            mma16(acc[1], __float_as_uint(av.x), __float_as_uint(av.y),
                  __float_as_uint(av.z), __float_as_uint(av.w),
                  Bf[c][1][0], Bf[c][1][1]);
        }
#pragma unroll
        for (int nn = 0; nn < 2; ++nn) {
            const int col = n0 + nn * 8 + 2 * tg;
            const float pb0 = BIAS[320 + col], pb1 = BIAS[320 + col + 1];
#pragma unroll
            for (int h = 0; h < 2; ++h) {
                const int row = mt * 16 + g + 8 * h;     // token t0 + row
                const float d0 = acc[nn][2 * h + 0] + pb0;
                const float d1 = acc[nn][2 * h + 1] + pb1;
                const float g0 = sigm(d0 * sigm(d0));
                const float g1 = sigm(d1 * sigm(d1));
                const float2 xv = *(const float2*)(x + xbase + (long)row * 64 + col);
                float2 o = make_float2(xv.x + g0 * d0, xv.y + g1 * d1);
                *(float2*)(out + xbase + (long)row * 64 + col) = o;
            }
        }
    }
}

extern "C" void kernel_launch(void* const* d_in, const int* in_sizes, int n_in,
                              void* d_out, int out_size)
{
    const float* x      = (const float*)d_in[0];
    const float* norm_g = (const float*)d_in[1];
    const float* qw  = (const float*)d_in[2];
    const float* qb  = (const float*)d_in[3];
    const float* kw  = (const float*)d_in[4];
    const float* kb  = (const float*)d_in[5];
    const float* vw  = (const float*)d_in[6];
    const float* vb  = (const float*)d_in[7];
    const float* qcw = (const float*)d_in[8];
    const float* qcb = (const float*)d_in[9];
    const float* kcw = (const float*)d_in[10];
    const float* kcb = (const float*)d_in[11];
    const float* vcw = (const float*)d_in[12];
    const float* vcb = (const float*)d_in[13];
    const float* aw  = (const float*)d_in[14];
    const float* ab  = (const float*)d_in[15];
    const float* bw  = (const float*)d_in[16];
    const float* bb  = (const float*)d_in[17];
    const float* png = (const float*)d_in[18];
    const float* pw  = (const float*)d_in[19];
    const float* pb  = (const float*)d_in[20];
    float* out = (float*)d_out;

    cudaFuncSetAttribute(gdn_kernel, cudaFuncAttributeMaxDynamicSharedMemorySize, SMEM_BYTES);
    gdn_kernel<<<4096, 320, SMEM_BYTES>>>(
        x, norm_g, qw, qb, kw, kb, vw, vb, qcw, qcb, kcw, kcb, vcw, vcb,
        aw, ab, bw, bb, png, pw, pb, out);
}

// round 11
// speedup vs baseline: 2.4738x; 1.1752x over previous
#include <cuda_runtime.h>
#include <cuda_fp16.h>
#include <cstdint>

// B=64, T=4096, D=64. Token tile 64 (+2 halo rows), M padded to 80 (5 m16-tiles).
// 320 threads = 10 warps, 3 CTAs/SM (smem 74976 B, launch_bounds(320,3)).
// GEMMs: mma.sync m16n8k16 fp16 (fp32 accum). A operands in packed-half2 fragment
// layout: per m16-tile, 4 k16-chunks, each lane one float4, chunk stride 132 words.
#define TSLOTW 528         // words (b32) per m16 tile: 4 chunks x 132
#define PST 68             // preactivation row stride (elements)

// shared memory byte offsets (params stay in global — L1-resident)
#define OFF_XF   0                  // 10560 B (x, fp16 frags)
#define OFF_HF   10560              // 10560 B (h / delta-norm, fp16 frags)
#define OFF_BP   21120              // 17952 B (b-linear preact, fp32)
#define OFF_QKVA 39072              // 35904 B (4 x 66x68 fp16 preacts)
#define SMEM_BYTES 74976

// fast sigmoid / tanh (MUFU-based; |args| here are O(1..10))
__device__ __forceinline__ float sigm(float z) {
    return __fdividef(1.0f, 1.0f + __expf(-z));
}
__device__ __forceinline__ float tanh_fast(float a) {
    const float t = __expf(2.0f * a);
    return __fdividef(t - 1.0f, t + 1.0f);
}

// interleaved 2-value butterfly reduction (one latency chain for two sums)
__device__ __forceinline__ void wredsum2(float& a, float& b) {
#pragma unroll
    for (int o = 16; o; o >>= 1) {
        a += __shfl_xor_sync(0xffffffffu, a, o);
        b += __shfl_xor_sync(0xffffffffu, b, o);
    }
}

__device__ __forceinline__ unsigned packh2(float lo, float hi) {
    __half2 h = __floats2half2_rn(lo, hi);
    return *(unsigned*)&h;
}

// store packed half2 for adjacent cols (2*lane, 2*lane+1) at row bits gd/hi
__device__ __forceinline__ void frag_store_w(float* tile, int gd, int hi, int lane, unsigned w) {
    const int c = 2 * lane;
    const int cc = c & 15;
    const int word = (c >> 4) * 132 + (4 * gd + ((cc & 7) >> 1)) * 4 + hi + 2 * (cc >> 3);
    ((unsigned*)tile)[word] = w;
}

__device__ __forceinline__ void mma16(float* d, unsigned a0, unsigned a1, unsigned a2, unsigned a3,
                                      unsigned b0, unsigned b1) {
    asm("mma.sync.aligned.m16n8k16.row.col.f32.f16.f16.f32 "
        "{%0,%1,%2,%3}, {%4,%5,%6,%7}, {%8,%9}, {%0,%1,%2,%3};"
        : "+f"(d[0]), "+f"(d[1]), "+f"(d[2]), "+f"(d[3])
        : "r"(a0), "r"(a1), "r"(a2), "r"(a3), "r"(b0), "r"(b1));
}

// Load k64 x n16 B-fragments from global W [64 out x 64 in], fp16-packed.
__device__ __forceinline__ void load_bfrag(const float* __restrict__ W, int n0, int g, int tg,
                                           unsigned Bf[4][2][2]) {
    const float* r0 = W + (n0 + g) * 64 + 2 * tg;
    const float* r1 = W + (n0 + g + 8) * 64 + 2 * tg;
#pragma unroll
    for (int c = 0; c < 4; ++c) {
        const float2 v00 = *(const float2*)(r0 + 16 * c);
        const float2 v01 = *(const float2*)(r0 + 16 * c + 8);
        const float2 v10 = *(const float2*)(r1 + 16 * c);
        const float2 v11 = *(const float2*)(r1 + 16 * c + 8);
        Bf[c][0][0] = packh2(v00.x, v00.y);
        Bf[c][0][1] = packh2(v01.x, v01.y);
        Bf[c][1][0] = packh2(v10.x, v10.y);
        Bf[c][1][1] = packh2(v11.x, v11.y);
    }
}

__global__ void __launch_bounds__(320, 3) gdn_kernel(
    const float* __restrict__ x,   const float* __restrict__ norm_g,
    const float* __restrict__ qw,  const float* __restrict__ qb,
    const float* __restrict__ kw,  const float* __restrict__ kb,
    const float* __restrict__ vw,  const float* __restrict__ vb,
    const float* __restrict__ qcw, const float* __restrict__ qcb,
    const float* __restrict__ kcw, const float* __restrict__ kcb,
    const float* __restrict__ vcw, const float* __restrict__ vcb,
    const float* __restrict__ aw,  const float* __restrict__ ab,
    const float* __restrict__ bw,  const float* __restrict__ bb,
    const float* __restrict__ png, const float* __restrict__ pw,
    const float* __restrict__ pb,  float* __restrict__ out)
{
    extern __shared__ char smc[];
    float* XF   = (float*)(smc + OFF_XF);
    float* HF   = (float*)(smc + OFF_HF);
    float* BPf  = (float*)(smc + OFF_BP);
    __half* QKVA = (__half*)(smc + OFF_QKVA);

    const int tid  = threadIdx.x;
    const int warp = tid >> 5;
    const int lane = tid & 31;
    const int g    = lane >> 2;
    const int tg   = lane & 3;
    const int b    = blockIdx.x >> 6;
    const int t0   = (blockIdx.x & 63) << 6;
    const long xbase = ((long)b * 4096 + t0) * 64;
    const bool zlo = (t0 == 0), zhi = (t0 + 64 == 4096);

    // ---- x load + zc_rmsnorm -> XF/HF fp16 frags; channels (2*lane, 2*lane+1) ----
    {
        const float2 ng2 = *(const float2*)(norm_g + 2 * lane);
        for (int r = warp; r < 80; r += 10) {
            const int gt = t0 - 1 + r;
            const bool valid = (r < 66) && (gt >= 0) && (gt < 4096);
            float a = 0.f, bv = 0.f;
            if (valid) {
                const float2 xv = *(const float2*)(x + ((long)b * 4096 + gt) * 64 + 2 * lane);
                a = xv.x; bv = xv.y;
            }
            const int mt = r >> 4, gd = r & 7, hi = (r >> 3) & 1;
            frag_store_w(XF + mt * TSLOTW, gd, hi, lane, packh2(a, bv));
            float s1 = a + bv, s2 = a * a + bv * bv;
            wredsum2(s1, s2);
            const float mean = s1 * (1.0f / 64.0f);
            const float var  = s2 * (1.0f / 64.0f) - mean * mean;
            const float inv  = rsqrtf(var + 1e-8f);
            frag_store_w(HF + mt * TSLOTW, gd, hi, lane,
                         packh2((a - mean) * inv * ng2.x, (bv - mean) * inv * ng2.y));
        }
    }
    __syncthreads();

    // ---- phase-1: 20 jobs = (matrix 0..4) x (n16 chunk 0..3); 2 jobs/warp ----
    {
        const float* wsrc[5] = { qw, kw, vw, aw, bw };
        const float* bsrc[5] = { qb, kb, vb, ab, bb };
#pragma unroll
        for (int jj = 0; jj < 2; ++jj) {
            const int job = warp + 10 * jj;
            const int mat = job >> 2;          // 0..4
            const int n0  = (job & 3) * 16;
            const float* AF = (mat < 3) ? HF : XF;

            unsigned Bf[4][2][2];
            load_bfrag(wsrc[mat], n0, g, tg, Bf);

            // hoist biases (global, L1-hit)
            float bA[2][2];
#pragma unroll
            for (int nn = 0; nn < 2; ++nn) {
                const float2 bv2 = *(const float2*)(bsrc[mat] + n0 + nn * 8 + 2 * tg);
                bA[nn][0] = bv2.x; bA[nn][1] = bv2.y;
            }

            const bool qkv = (mat < 3);
            __half* Ob = QKVA + mat * (66 * PST);   // valid for mat<4

#pragma unroll
            for (int mt = 0; mt < 5; ++mt) {
                const float4* Afp = (const float4*)(AF + mt * TSLOTW);
                float acc[2][4];
#pragma unroll
                for (int i = 0; i < 2; ++i)
#pragma unroll
                    for (int j = 0; j < 4; ++j) acc[i][j] = 0.f;

#pragma unroll
                for (int c = 0; c < 4; ++c) {
                    const float4 av = Afp[c * 33 + lane];
                    const unsigned a0 = __float_as_uint(av.x);
                    const unsigned a1 = __float_as_uint(av.y);
                    const unsigned a2 = __float_as_uint(av.z);
                    const unsigned a3 = __float_as_uint(av.w);
                    mma16(acc[0], a0, a1, a2, a3, Bf[c][0][0], Bf[c][0][1]);
                    mma16(acc[1], a0, a1, a2, a3, Bf[c][1][0], Bf[c][1][1]);
                }
                const int rA = mt * 16 + g, rB = rA + 8;
#pragma unroll
                for (int nn = 0; nn < 2; ++nn) {
                    const int c0 = n0 + nn * 8 + 2 * tg;
#pragma unroll
                    for (int rr = 0; rr < 2; ++rr) {
                        const int r = rr ? rB : rA;
                        if (r >= 66) continue;
                        float v0 = acc[nn][2 * rr + 0] + bA[nn][0];
                        float v1 = acc[nn][2 * rr + 1] + bA[nn][1];
                        if (qkv && ((zlo && r == 0) || (zhi && r == 65))) { v0 = 0.f; v1 = 0.f; }
                        if (mat < 4) {
                            *(__half2*)(Ob + r * PST + c0) = __floats2half2_rn(v0, v1);
                        } else {
                            *(float2*)(BPf + r * PST + c0) = make_float2(v0, v1);
                        }
                    }
                }
            }
        }
    }
    __syncthreads();

    // ---- per-token stage; channels (2*lane, 2*lane+1), register-carried stencil ----
    // warps 0..3: 7 tokens from s=1+7w; warps 4..9: 6 tokens from s=29+6(w-4)
    {
        const __half* QP = QKVA;
        const __half* KP = QKVA + 66 * PST;
        const __half* VP = QKVA + 2 * 66 * PST;
        const __half* AP = QKVA + 3 * 66 * PST;
        const int s   = (warp < 4) ? (1 + 7 * warp) : (29 + 6 * (warp - 4));
        const int cnt = (warp < 4) ? 7 : 6;
        const int cc0 = 2 * lane;

        // conv params from global (once per warp)
        float cwq[3][2], cwk[3][2], cwv[3][2];
#pragma unroll
        for (int tap = 0; tap < 3; ++tap) {
            cwq[tap][0] = qcw[cc0 * 3 + tap];  cwq[tap][1] = qcw[(cc0 + 1) * 3 + tap];
            cwk[tap][0] = kcw[cc0 * 3 + tap];  cwk[tap][1] = kcw[(cc0 + 1) * 3 + tap];
            cwv[tap][0] = vcw[cc0 * 3 + tap];  cwv[tap][1] = vcw[(cc0 + 1) * 3 + tap];
        }
        const float2 cbq = *(const float2*)(qcb + cc0);
        const float2 cbk = *(const float2*)(kcb + cc0);
        const float2 cbv = *(const float2*)(vcb + cc0);
        const float2 pg2 = *(const float2*)(png + cc0);

        float qm[2], q0[2], km[2], k0[2], vm[2], v0[2];
        {
            const float2 qa = __half22float2(*(const __half2*)(QP + (s - 1) * PST + cc0));
            const float2 qbv = __half22float2(*(const __half2*)(QP + s * PST + cc0));
            const float2 ka = __half22float2(*(const __half2*)(KP + (s - 1) * PST + cc0));
            const float2 kbv = __half22float2(*(const __half2*)(KP + s * PST + cc0));
            const float2 va = __half22float2(*(const __half2*)(VP + (s - 1) * PST + cc0));
            const float2 vbv = __half22float2(*(const __half2*)(VP + s * PST + cc0));
            qm[0] = qa.x; qm[1] = qa.y; q0[0] = qbv.x; q0[1] = qbv.y;
            km[0] = ka.x; km[1] = ka.y; k0[0] = kbv.x; k0[1] = kbv.y;
            vm[0] = va.x; vm[1] = va.y; v0[0] = vbv.x; v0[1] = vbv.y;
        }

        for (int t = s; t < s + cnt; ++t) {
            const float2 qpv = __half22float2(*(const __half2*)(QP + (t + 1) * PST + cc0));
            const float2 kpv = __half22float2(*(const __half2*)(KP + (t + 1) * PST + cc0));
            const float2 vpv = __half22float2(*(const __half2*)(VP + (t + 1) * PST + cc0));
            const float qp[2] = { qpv.x, qpv.y };
            const float kp[2] = { kpv.x, kpv.y };
            const float vp[2] = { vpv.x, vpv.y };
            float qv[2], kv[2], vv[2];
#pragma unroll
            for (int h = 0; h < 2; ++h) {
                qv[h] = sigm(cwq[0][h] * qm[h] + cwq[1][h] * q0[h] + cwq[2][h] * qp[h] + (h ? cbq.y : cbq.x));
                kv[h] = sigm(cwk[0][h] * km[h] + cwk[1][h] * k0[h] + cwk[2][h] * kp[h] + (h ? cbk.y : cbk.x));
                vv[h] = sigm(cwv[0][h] * vm[h] + cwv[1][h] * v0[h] + cwv[2][h] * vp[h] + (h ? cbv.y : cbv.x));
            }
            float qs = qv[0] * qv[0] + qv[1] * qv[1];
            float ks = kv[0] * kv[0] + kv[1] * kv[1];
            wredsum2(qs, ks);
            const float qi = rsqrtf(qs + 1e-8f);
            const float ki = rsqrtf(ks + 1e-8f);
            const float2 av2 = __half22float2(*(const __half2*)(AP + t * PST + cc0));
            const float2 bp2 = *(const float2*)(BPf + t * PST + cc0);
            float d2[2];
            d2[0] = tanh_fast(av2.x) * ((qv[0] * qi) * ((kv[0] * ki) * vv[0])) + bp2.x;
            d2[1] = tanh_fast(av2.y) * ((qv[1] * qi) * ((kv[1] * ki) * vv[1])) + bp2.y;
            float s1 = d2[0] + d2[1], s2 = d2[0] * d2[0] + d2[1] * d2[1];
            wredsum2(s1, s2);
            const float mean = s1 * (1.0f / 64.0f);
            const float var  = s2 * (1.0f / 64.0f) - mean * mean;
            const float inv  = rsqrtf(var + 1e-8f);
            const int tk = t - 1;
            const int mt = tk >> 4, gd = tk & 7, hi = (tk >> 3) & 1;
            frag_store_w(HF + mt * TSLOTW, gd, hi, lane,
                         packh2((d2[0] - mean) * inv * pg2.x, (d2[1] - mean) * inv * pg2.y));
#pragma unroll
            for (int h = 0; h < 2; ++h) {
                qm[h] = q0[h]; q0[h] = qp[h];
                km[h] = k0[h]; k0[h] = kp[h];
                vm[h] = v0[h]; v0[h] = vp[h];
            }
        }
    }
    __syncthreads();

    // ---- final GEMM: 16 jobs m16 x n16 x k64; warps 0..5 do 2 jobs, 6..9 one ----
    for (int job = warp; job < 16; job += 10) {
        const int mt = job >> 2;
        const int n0 = (job & 3) * 16;

        unsigned Bf[4][2][2];
        load_bfrag(pw, n0, g, tg, Bf);

        const float4* Afp = (const float4*)(HF + mt * TSLOTW);
        float acc[2][4];
#pragma unroll
        for (int i = 0; i < 2; ++i)
#pragma unroll
            for (int j = 0; j < 4; ++j) acc[i][j] = 0.f;

#pragma unroll
        for (int c = 0; c < 4; ++c) {
            const float4 av = Afp[c * 33 + lane];
            mma16(acc[0], __float_as_uint(av.x), __float_as_uint(av.y),
                  __float_as_uint(av.z), __float_as_uint(av.w),
                  Bf[c][0][0], Bf[c][0][1]);
            mma16(acc[1], __float_as_uint(av.x), __float_as_uint(av.y),
                  __float_as_uint(av.z), __float_as_uint(av.w),
                  Bf[c][1][0], Bf[c][1][1]);
        }
#pragma unroll
        for (int nn = 0; nn < 2; ++nn) {
            const int col = n0 + nn * 8 + 2 * tg;
            const float2 pb2 = *(const float2*)(pb + col);
#pragma unroll
            for (int h = 0; h < 2; ++h) {
                const int row = mt * 16 + g + 8 * h;     // token t0 + row
                const float d0 = acc[nn][2 * h + 0] + pb2.x;
                const float d1 = acc[nn][2 * h + 1] + pb2.y;
                const float g0 = sigm(d0 * sigm(d0));
                const float g1 = sigm(d1 * sigm(d1));
                const float2 xv = *(const float2*)(x + xbase + (long)row * 64 + col);
                float2 o = make_float2(xv.x + g0 * d0, xv.y + g1 * d1);
                *(float2*)(out + xbase + (long)row * 64 + col) = o;
            }
        }
    }
}

extern "C" void kernel_launch(void* const* d_in, const int* in_sizes, int n_in,
                              void* d_out, int out_size)
{
    const float* x      = (const float*)d_in[0];
    const float* norm_g = (const float*)d_in[1];
    const float* qw  = (const float*)d_in[2];
    const float* qb  = (const float*)d_in[3];
    const float* kw  = (const float*)d_in[4];
    const float* kb  = (const float*)d_in[5];
    const float* vw  = (const float*)d_in[6];
    const float* vb  = (const float*)d_in[7];
    const float* qcw = (const float*)d_in[8];
    const float* qcb = (const float*)d_in[9];
    const float* kcw = (const float*)d_in[10];
    const float* kcb = (const float*)d_in[11];
    const float* vcw = (const float*)d_in[12];
    const float* vcb = (const float*)d_in[13];
    const float* aw  = (const float*)d_in[14];
    const float* ab  = (const float*)d_in[15];
    const float* bw  = (const float*)d_in[16];
    const float* bb  = (const float*)d_in[17];
    const float* png = (const float*)d_in[18];
    const float* pw  = (const float*)d_in[19];
    const float* pb  = (const float*)d_in[20];
    float* out = (float*)d_out;

    cudaFuncSetAttribute(gdn_kernel, cudaFuncAttributeMaxDynamicSharedMemorySize, SMEM_BYTES);
    gdn_kernel<<<4096, 320, SMEM_BYTES>>>(
        x, norm_g, qw, qb, kw, kb, vw, vb, qcw, qcb, kcw, kcb, vcw, vcb,
        aw, ab, bw, bb, png, pw, pb, out);
}